// round 8
// baseline (speedup 1.0000x reference)
#include <cuda_runtime.h>
#include <cuda_bf16.h>
#include <mma.h>
#include <cstdint>

using namespace nvcuda;

#define Bsz 8
#define Nn 1024
#define Ee 256
#define Dm 64
#define Hh 4
#define DH 16

// ======================= device scratch =======================
__device__ float d_qk[2][Bsz][Hh][DH][Nn];                 // q, k transposed [c][n]
__device__ float d_e [4][Bsz][Hh][Ee][DH];                 // eq, ek, ceq, cek
// MMA-ready padded bf16 rows (64 cols = 128B each):
//   d_ga row: [qhi(16) | qhi(16) | qlo(16) | 0(16)]   (gq pre-scaled by 1/8)
//   d_gb row: [khi(16) | klo(16) | khi(16) | 0(16)]
// => dot over k=0..47 = qhi*khi + qhi*klo + qlo*khi  (3-term bf16 split, err ~1e-5)
__device__ __nv_bfloat16 d_ga[2][Bsz][Hh][Nn][64];
__device__ __nv_bfloat16 d_gb[2][Bsz][Hh][Nn][64];

// ---------------- K1: emb -> q,k (transposed) ----------------
__global__ void k_qk(const float* __restrict__ x,
                     const float* __restrict__ W_emb, const float* __restrict__ b_emb,
                     const float* __restrict__ W_q,   const float* __restrict__ b_q,
                     const float* __restrict__ W_k,   const float* __restrict__ b_k) {
    int bn  = blockIdx.x;
    int tid = threadIdx.x;         // 0..63
    __shared__ float emb[64];
    float x0 = x[bn * 2 + 0];
    float x1 = x[bn * 2 + 1];
    emb[tid] = x0 * W_emb[tid] + x1 * W_emb[64 + tid] + b_emb[tid];
    __syncthreads();
    float q = b_q[tid], k = b_k[tid];
#pragma unroll
    for (int j = 0; j < 64; ++j) {
        float e = emb[j];
        q = fmaf(e, W_q[j * 64 + tid], q);
        k = fmaf(e, W_k[j * 64 + tid], k);
    }
    int b = bn >> 10, n = bn & 1023;
    int h = tid >> 4, c = tid & 15;
    d_qk[0][b][h][c][n] = q;
    d_qk[1][b][h][c][n] = k;
}

// ---------------- K2: edge projections ----------------
__global__ void k_edge(const float* __restrict__ edge, const float* __restrict__ cedge,
                       const float* __restrict__ W_eq,  const float* __restrict__ b_eq,
                       const float* __restrict__ W_ek,  const float* __restrict__ b_ek,
                       const float* __restrict__ W_ceq, const float* __restrict__ b_ceq,
                       const float* __restrict__ W_cek, const float* __restrict__ b_cek) {
    int i = blockIdx.x * blockDim.x + threadIdx.x;
    int c = i & 15;
    int r = (i >> 4) & 8191;
    int t = i >> 17;
    const float* src = (t < 2 ? edge : cedge) + r * 16;
    const float* W; const float* bb;
    if      (t == 0) { W = W_eq;  bb = b_eq;  }
    else if (t == 1) { W = W_ek;  bb = b_ek;  }
    else if (t == 2) { W = W_ceq; bb = b_ceq; }
    else             { W = W_cek; bb = b_cek; }
    float a = bb[c];
#pragma unroll
    for (int j = 0; j < 16; ++j) a = fmaf(src[j], W[j * 16 + c], a);
    (&d_e[0][0][0][0][0])[i] = a;
}

// ---------------- K3: gq/gk + div + bf16 hi/lo MMA-format emit ----------------
// grid: 2br * 8b * 16nt = 256 blocks; 1024 threads = 16 c x 64 n
__global__ void __launch_bounds__(1024, 1)
k_gextra(const float* __restrict__ G, const float* __restrict__ CG) {
    int bid = blockIdx.x;
    int nt = bid & 15;  bid >>= 4;
    int b  = bid & 7;   bid >>= 3;
    int br = bid;
    int tid = threadIdx.x;
    int c    = tid >> 6;        // 0..15
    int nloc = tid & 63;        // 0..63
    int nbase = nt * 64;

    const float* Gm  = (br ? CG : G) + (size_t)b * Ee * Nn;
    const float* eqb = &d_e[br * 2 + 0][b][0][0][0];   // [h][e][c]
    const float* ekb = &d_e[br * 2 + 1][b][0][0][0];

    __shared__ float sg[16][64];
    __shared__ float seq[4][16][16];
    __shared__ float sek[4][16][16];
    __shared__ float sq [4][64][16];    // results [h][nloc][c]
    __shared__ float sk2[4][64][16];

    float aq[4] = {0.f, 0.f, 0.f, 0.f};
    float ak[4] = {0.f, 0.f, 0.f, 0.f};
    float gsum = 0.f;

    for (int e0 = 0; e0 < Ee; e0 += 16) {
        __syncthreads();
        {
            int se = tid >> 6, sn = tid & 63;
            sg[se][sn] = Gm[(size_t)(e0 + se) * Nn + nbase + sn];
            int sh = tid >> 8, see = (tid >> 4) & 15, sc = tid & 15;
            seq[sh][see][sc] = eqb[(sh * Ee + e0 + see) * DH + sc];
            sek[sh][see][sc] = ekb[(sh * Ee + e0 + see) * DH + sc];
        }
        __syncthreads();
#pragma unroll
        for (int ee = 0; ee < 16; ++ee) {
            float g = sg[ee][nloc];
            gsum += g;
#pragma unroll
            for (int h = 0; h < 4; ++h) {
                aq[h] = fmaf(g, seq[h][ee][c], aq[h]);
                ak[h] = fmaf(g, sek[h][ee][c], ak[h]);
            }
        }
    }
    float rd = 1.0f / gsum;
    int n = nbase + nloc;
#pragma unroll
    for (int h = 0; h < 4; ++h) {
        float q = d_qk[0][b][h][c][n];
        float k = d_qk[1][b][h][c][n];
        sq [h][nloc][c] = (q + aq[h] * rd) * 0.125f;   // fold 1/sqrt(64)
        sk2[h][nloc][c] = (k + ak[h] * rd);
    }
    __syncthreads();

    // emit: 1024 threads -> 512 jobs x 2 halves. job = (h, nloc, qk); half = 32 bf16 (64B).
    {
        int half = tid & 1;
        int job  = tid >> 1;
        int qk   = job & 1;
        int nl   = (job >> 1) & 63;
        int h    = job >> 7;
        const float* src = qk ? &sk2[h][nl][0] : &sq[h][nl][0];
        __nv_bfloat16 hi[16]; __nv_bfloat16 lo[16];
#pragma unroll
        for (int j = 0; j < 16; ++j) {
            float v = src[j];
            hi[j] = __float2bfloat16(v);
            lo[j] = __float2bfloat16(v - __bfloat162float(hi[j]));
        }
        uint32_t u[16];
        if (half == 0) {
            // cols 0-31:  A: hi|hi   B: hi|lo
#pragma unroll
            for (int j = 0; j < 8; ++j)
                u[j] = (uint32_t)__bfloat16_as_ushort(hi[2 * j]) |
                       ((uint32_t)__bfloat16_as_ushort(hi[2 * j + 1]) << 16);
#pragma unroll
            for (int j = 0; j < 8; ++j) {
                __nv_bfloat16 a  = qk ? lo[2 * j]     : hi[2 * j];
                __nv_bfloat16 bq = qk ? lo[2 * j + 1] : hi[2 * j + 1];
                u[8 + j] = (uint32_t)__bfloat16_as_ushort(a) |
                           ((uint32_t)__bfloat16_as_ushort(bq) << 16);
            }
        } else {
            // cols 32-63: A: lo|0   B: hi|0
#pragma unroll
            for (int j = 0; j < 8; ++j) {
                __nv_bfloat16 a  = qk ? hi[2 * j]     : lo[2 * j];
                __nv_bfloat16 bq = qk ? hi[2 * j + 1] : lo[2 * j + 1];
                u[j] = (uint32_t)__bfloat16_as_ushort(a) |
                       ((uint32_t)__bfloat16_as_ushort(bq) << 16);
            }
#pragma unroll
            for (int j = 0; j < 8; ++j) u[8 + j] = 0u;
        }
        __nv_bfloat16* dstb = qk ? &d_gb[br][b][h][nbase + nl][0] : &d_ga[br][b][h][nbase + nl][0];
        uint4* dst = (uint4*)(dstb + half * 32);
        dst[0] = make_uint4(u[0], u[1], u[2], u[3]);
        dst[1] = make_uint4(u[4], u[5], u[6], u[7]);
        dst[2] = make_uint4(u[8], u[9], u[10], u[11]);
        dst[3] = make_uint4(u[12], u[13], u[14], u[15]);
    }
}

// ---------------- K4: scores via wmma, smem-staged operands ----------------
// grid: 2br*8b*4h*32rowchunk(32 rows) = 2048 blocks; 512 threads (16 warps).
// Warp (wr, wc): rows wr*16..+15, cols wc*128..+127 (8 n-tiles). K=48 (3 k-steps).
// B (1024x64 bf16) + A (32x64) staged in smem, ldm 72 (conflict-free ldmatrix).
// Acc fragments stay live in registers across rowsum merge; small per-warp buffer.
#define LDA 72
#define B_BYTES (1024 * LDA * 2)     // 147456
#define A_BYTES (32 * LDA * 2)       // 4608
__global__ void __launch_bounds__(512, 1)
k_attn(float* __restrict__ out) {
    int bid = blockIdx.x;
    int rc = bid & 31;  bid >>= 5;
    int h  = bid & 3;   bid >>= 2;
    int b  = bid & 7;   bid >>= 3;
    int br = bid;
    int rbase = rc * 32;

    extern __shared__ char dyn[];
    __nv_bfloat16* sB = (__nv_bfloat16*)dyn;                    // [1024][72]
    __nv_bfloat16* sA = (__nv_bfloat16*)(dyn + B_BYTES);        // [32][72]
    float* bufs = (float*)(dyn + B_BYTES + A_BYTES);            // 16 warps x 320 floats
    __shared__ float s_part[8][32];
    __shared__ float s_inv[32];

    int tid = threadIdx.x;
    int warp = tid >> 5, lane = tid & 31;
    int wr = warp >> 3, wc = warp & 7;

    // stage B: 1024 rows x 8 uint4 -> padded 9-uint4 rows
    {
        const uint4* gb4 = (const uint4*)&d_gb[br][b][h][0][0];
        uint4* sB4 = (uint4*)sB;
        for (int i = tid; i < 8192; i += 512)
            sB4[(i >> 3) * 9 + (i & 7)] = gb4[i];
    }
    // stage A: 32 rows x 8 uint4
    if (tid < 256) {
        const uint4* ga4 = (const uint4*)&d_ga[br][b][h][rbase][0];
        uint4* sA4 = (uint4*)sA;
        sA4[(tid >> 3) * 9 + (tid & 7)] = ga4[tid];
    }
    __syncthreads();

    wmma::fragment<wmma::matrix_a, 16, 16, 16, __nv_bfloat16, wmma::row_major> af[3];
#pragma unroll
    for (int s = 0; s < 3; ++s)
        wmma::load_matrix_sync(af[s], sA + wr * 16 * LDA + s * 16, LDA);

    wmma::fragment<wmma::accumulator, 16, 16, 16, float> accs[8];
    float* mybuf = bufs + warp * 320;            // 16 x 20
    float rsum = 0.f;

#pragma unroll
    for (int t = 0; t < 8; ++t) {
        int n0 = wc * 128 + t * 16;
        wmma::fragment<wmma::matrix_b, 16, 16, 16, __nv_bfloat16, wmma::col_major> bf0, bf1, bf2;
        wmma::load_matrix_sync(bf0, sB + n0 * LDA + 0,  LDA);
        wmma::load_matrix_sync(bf1, sB + n0 * LDA + 16, LDA);
        wmma::load_matrix_sync(bf2, sB + n0 * LDA + 32, LDA);
        wmma::fill_fragment(accs[t], 0.0f);
        wmma::mma_sync(accs[t], af[0], bf0, accs[t]);
        wmma::mma_sync(accs[t], af[1], bf1, accs[t]);
        wmma::mma_sync(accs[t], af[2], bf2, accs[t]);
#pragma unroll
        for (int e = 0; e < accs[t].num_elements; ++e)
            accs[t].x[e] = __expf(accs[t].x[e]);   // no max: shift-invariant, bounded scores
        // partial rowsum via small buffer
        wmma::store_matrix_sync(mybuf, accs[t], 20, wmma::mem_row_major);
        __syncwarp();
        if (lane < 16) {
            float s = 0.f;
#pragma unroll
            for (int c = 0; c < 16; ++c) s += mybuf[lane * 20 + c];
            rsum += s;
        }
        __syncwarp();
    }
    if (lane < 16) s_part[wc][wr * 16 + lane] = rsum;
    __syncthreads();
    if (tid < 32) {
        float S = 0.f;
#pragma unroll
        for (int w = 0; w < 8; ++w) S += s_part[w][tid];
        s_inv[tid] = 1.0f / S;
    }
    __syncthreads();

    // pass 2: scale + coalesced stores
    size_t obase = ((((size_t)br * Bsz + b) * Hh + h) * Nn + rbase) * (size_t)Nn;
    int r    = lane >> 1;
    int halfc = (lane & 1) << 3;
    float inv = s_inv[wr * 16 + r];
    size_t rowoff = obase + (size_t)(wr * 16 + r) * Nn + wc * 128 + halfc;
#pragma unroll
    for (int t = 0; t < 8; ++t) {
        wmma::store_matrix_sync(mybuf, accs[t], 20, wmma::mem_row_major);
        __syncwarp();
        float4 v0 = *(const float4*)&mybuf[r * 20 + halfc];
        float4 v1 = *(const float4*)&mybuf[r * 20 + halfc + 4];
        v0.x *= inv; v0.y *= inv; v0.z *= inv; v0.w *= inv;
        v1.x *= inv; v1.y *= inv; v1.z *= inv; v1.w *= inv;
        *(float4*)(out + rowoff + t * 16)     = v0;
        *(float4*)(out + rowoff + t * 16 + 4) = v1;
        __syncwarp();
    }
}

// ---------------- launcher ----------------
extern "C" void kernel_launch(void* const* d_in, const int* in_sizes, int n_in,
                              void* d_out, int out_size) {
    const float* x      = (const float*)d_in[0];
    const float* edge   = (const float*)d_in[1];
    const float* cedge  = (const float*)d_in[2];
    const float* G      = (const float*)d_in[3];
    const float* CG     = (const float*)d_in[4];
    const float* W_emb  = (const float*)d_in[5];
    const float* b_emb  = (const float*)d_in[6];
    const float* W_q    = (const float*)d_in[7];
    const float* b_q    = (const float*)d_in[8];
    const float* W_k    = (const float*)d_in[9];
    const float* b_k    = (const float*)d_in[10];
    const float* W_eq   = (const float*)d_in[11];
    const float* b_eq   = (const float*)d_in[12];
    const float* W_ek   = (const float*)d_in[13];
    const float* b_ek   = (const float*)d_in[14];
    const float* W_ceq  = (const float*)d_in[15];
    const float* b_ceq  = (const float*)d_in[16];
    const float* W_cek  = (const float*)d_in[17];
    const float* b_cek  = (const float*)d_in[18];
    float* out = (float*)d_out;

    int dynBytes = B_BYTES + A_BYTES + 16 * 320 * 4;   // 172544 + 20480 = 193024? (see below)
    cudaFuncSetAttribute(k_attn, cudaFuncAttributeMaxDynamicSharedMemorySize, dynBytes);

    k_qk<<<Bsz * Nn, 64>>>(x, W_emb, b_emb, W_q, b_q, W_k, b_k);
    k_edge<<<2048, 256>>>(edge, cedge, W_eq, b_eq, W_ek, b_ek, W_ceq, b_ceq, W_cek, b_cek);
    k_gextra<<<256, 1024>>>(G, CG);
    k_attn<<<2048, 512, dynBytes>>>(out);
}

// round 9
// speedup vs baseline: 1.7438x; 1.7438x over previous
#include <cuda_runtime.h>
#include <cstdint>

#define Bsz 8
#define Nn 1024
#define Ee 256
#define Dm 64
#define Hh 4
#define DH 16

// fold 1/sqrt(64) * log2(e) into gq so scores feed ex2 directly
#define QSCALE 0.180336880520712f

// ---------------- device scratch (transposed layouts: [c][n]) ----------------
__device__ float d_qk[2][Bsz][Hh][DH][Nn];        // q, k  transposed
__device__ float d_e [4][Bsz][Hh][Ee][DH];        // eq, ek, ceq, cek
__device__ float d_g [2][2][Bsz][Hh][DH][Nn];     // [branch][q|k][b][h][c][n]

// ---------------- K1: emb -> q,k (stores transposed) ----------------
__global__ void k_qk(const float* __restrict__ x,
                     const float* __restrict__ W_emb, const float* __restrict__ b_emb,
                     const float* __restrict__ W_q,   const float* __restrict__ b_q,
                     const float* __restrict__ W_k,   const float* __restrict__ b_k) {
    int bn  = blockIdx.x;
    int tid = threadIdx.x;         // 0..63
    __shared__ float emb[64];
    float x0 = x[bn * 2 + 0];
    float x1 = x[bn * 2 + 1];
    emb[tid] = x0 * W_emb[tid] + x1 * W_emb[64 + tid] + b_emb[tid];
    __syncthreads();
    float q = b_q[tid], k = b_k[tid];
#pragma unroll
    for (int j = 0; j < 64; ++j) {
        float e = emb[j];
        q = fmaf(e, W_q[j * 64 + tid], q);
        k = fmaf(e, W_k[j * 64 + tid], k);
    }
    int b = bn >> 10, n = bn & 1023;
    int h = tid >> 4, c = tid & 15;
    d_qk[0][b][h][c][n] = q;
    d_qk[1][b][h][c][n] = k;
}

// ---------------- K2: edge projections ----------------
__global__ void k_edge(const float* __restrict__ edge, const float* __restrict__ cedge,
                       const float* __restrict__ W_eq,  const float* __restrict__ b_eq,
                       const float* __restrict__ W_ek,  const float* __restrict__ b_ek,
                       const float* __restrict__ W_ceq, const float* __restrict__ b_ceq,
                       const float* __restrict__ W_cek, const float* __restrict__ b_cek) {
    int i = blockIdx.x * blockDim.x + threadIdx.x;
    int c = i & 15;
    int r = (i >> 4) & 8191;
    int t = i >> 17;
    const float* src = (t < 2 ? edge : cedge) + r * 16;
    const float* W; const float* bb;
    if      (t == 0) { W = W_eq;  bb = b_eq;  }
    else if (t == 1) { W = W_ek;  bb = b_ek;  }
    else if (t == 2) { W = W_ceq; bb = b_ceq; }
    else             { W = W_cek; bb = b_cek; }
    float a = bb[c];
#pragma unroll
    for (int j = 0; j < 16; ++j) a = fmaf(src[j], W[j * 16 + c], a);
    (&d_e[0][0][0][0][0])[i] = a;
}

// ---------------- K3: gq/gk (transposed out) + div, one pass over G ----------------
// grid: 2br * 8b * 16ntile = 256 blocks; 1024 threads = 16 c x 64 n
__global__ void __launch_bounds__(1024, 2)
k_gextra(const float* __restrict__ G, const float* __restrict__ CG) {
    int bid = blockIdx.x;
    int nt = bid & 15;  bid >>= 4;
    int b  = bid & 7;   bid >>= 3;
    int br = bid;
    int tid = threadIdx.x;
    int c    = tid >> 6;        // 0..15
    int nloc = tid & 63;        // 0..63
    int nbase = nt * 64;

    const float* Gm  = (br ? CG : G) + (size_t)b * Ee * Nn;
    const float* eqb = &d_e[br * 2 + 0][b][0][0][0];   // [h][e][c]
    const float* ekb = &d_e[br * 2 + 1][b][0][0][0];

    __shared__ float sg[16][64];
    __shared__ float seq[4][16][16];
    __shared__ float sek[4][16][16];

    float aq[4] = {0.f, 0.f, 0.f, 0.f};
    float ak[4] = {0.f, 0.f, 0.f, 0.f};
    float gsum = 0.f;

    for (int e0 = 0; e0 < Ee; e0 += 16) {
        __syncthreads();
        {
            int se = tid >> 6, sn = tid & 63;
            sg[se][sn] = Gm[(size_t)(e0 + se) * Nn + nbase + sn];
            int sh = tid >> 8, see = (tid >> 4) & 15, sc = tid & 15;
            seq[sh][see][sc] = eqb[(sh * Ee + e0 + see) * DH + sc];
            sek[sh][see][sc] = ekb[(sh * Ee + e0 + see) * DH + sc];
        }
        __syncthreads();
#pragma unroll
        for (int ee = 0; ee < 16; ++ee) {
            float g = sg[ee][nloc];
            gsum += g;
#pragma unroll
            for (int h = 0; h < 4; ++h) {
                aq[h] = fmaf(g, seq[h][ee][c], aq[h]);
                ak[h] = fmaf(g, sek[h][ee][c], ak[h]);
            }
        }
    }
    float rd = 1.0f / gsum;
    int n = nbase + nloc;
#pragma unroll
    for (int h = 0; h < 4; ++h) {
        float q = d_qk[0][b][h][c][n];
        float k = d_qk[1][b][h][c][n];
        d_g[br][0][b][h][c][n] = (q + aq[h] * rd) * QSCALE;   // 1/8 * log2(e)
        d_g[br][1][b][h][c][n] = (k + ak[h] * rd);
    }
}

// ---------------- K4: scores + softmax, K-in-registers ----------------
// grid: 2br*8b*4h*32chunk(32 rows) = 2048 blocks; 256 threads (8 warps).
// Thread owns 4 consecutive k-cols (col0 = warp*128 + lane*4): k[16] float4 regs.
// Per row: 4 broadcast LDS.128 (q) + 64 FFMA in 4 independent chains + 4 ex2.
// Waves of 4 rows; exps stay in regs; 2 barriers per wave.
#define RCHUNK 32
__global__ void __launch_bounds__(256, 2)
k_attn(float* __restrict__ out) {
    int bid = blockIdx.x;
    int chunk = bid & 31;  bid >>= 5;
    int h     = bid & 3;   bid >>= 2;
    int b     = bid & 7;   bid >>= 3;
    int br    = bid;
    int rbase = chunk * RCHUNK;

    const float* gq = &d_g[br][0][b][h][0][0];   // [c][n]
    const float* gk = &d_g[br][1][b][h][0][0];   // [c][n]

    __shared__ float sq[RCHUNK][20];             // padded, 16B-aligned rows
    __shared__ float spart[8][4];                // [warp][row-in-wave]
    __shared__ float sinv[4];

    int tid  = threadIdx.x;
    int warp = tid >> 5, lane = tid & 31;
    int col0 = warp * 128 + lane * 4;

    // K columns into registers: 16 coalesced LDG.128 per thread
    float4 kk[16];
#pragma unroll
    for (int c = 0; c < 16; ++c)
        kk[c] = *(const float4*)(gk + c * Nn + col0);

    // stage Q chunk: [c][32] slab -> sq[r][c]
    for (int i = tid; i < RCHUNK * 16; i += 256) {
        int c = i >> 5, r = i & 31;
        sq[r][c] = gq[c * Nn + rbase + r];
    }
    __syncthreads();

    size_t obase = ((((size_t)br * Bsz + b) * Hh + h) * Nn + rbase) * (size_t)Nn;

#pragma unroll 1
    for (int wv = 0; wv < RCHUNK / 4; ++wv) {
        int r0 = wv * 4;
        float4 ex[4];
        float part[4];
#pragma unroll
        for (int rr = 0; rr < 4; ++rr) {
            const float* qp = &sq[r0 + rr][0];
            float4 qa = *(const float4*)(qp + 0);    // uniform-address broadcast
            float4 qb = *(const float4*)(qp + 4);
            float4 qc = *(const float4*)(qp + 8);
            float4 qd = *(const float4*)(qp + 12);
            float qv[16] = {qa.x, qa.y, qa.z, qa.w, qb.x, qb.y, qb.z, qb.w,
                            qc.x, qc.y, qc.z, qc.w, qd.x, qd.y, qd.z, qd.w};
            float s0 = 0.f, s1 = 0.f, s2 = 0.f, s3 = 0.f;
#pragma unroll
            for (int c = 0; c < 16; ++c) {
                s0 = fmaf(qv[c], kk[c].x, s0);
                s1 = fmaf(qv[c], kk[c].y, s1);
                s2 = fmaf(qv[c], kk[c].z, s2);
                s3 = fmaf(qv[c], kk[c].w, s3);
            }
            float e0, e1, e2, e3;                    // scores pre-scaled by log2e/8
            asm("ex2.approx.f32 %0, %1;" : "=f"(e0) : "f"(s0));
            asm("ex2.approx.f32 %0, %1;" : "=f"(e1) : "f"(s1));
            asm("ex2.approx.f32 %0, %1;" : "=f"(e2) : "f"(s2));
            asm("ex2.approx.f32 %0, %1;" : "=f"(e3) : "f"(s3));
            ex[rr] = make_float4(e0, e1, e2, e3);
            part[rr] = (e0 + e1) + (e2 + e3);
        }
#pragma unroll
        for (int o = 16; o; o >>= 1)
#pragma unroll
            for (int rr = 0; rr < 4; ++rr)
                part[rr] += __shfl_xor_sync(0xffffffffu, part[rr], o);
        if (lane == 0) {
#pragma unroll
            for (int rr = 0; rr < 4; ++rr) spart[warp][rr] = part[rr];
        }
        __syncthreads();
        if (tid < 4) {
            float s = 0.f;
#pragma unroll
            for (int w = 0; w < 8; ++w) s += spart[w][tid];
            sinv[tid] = 1.0f / s;
        }
        __syncthreads();
#pragma unroll
        for (int rr = 0; rr < 4; ++rr) {
            float iv = sinv[rr];
            float4 v = ex[rr];
            v.x *= iv; v.y *= iv; v.z *= iv; v.w *= iv;
            *(float4*)(out + obase + (size_t)(r0 + rr) * Nn + col0) = v;
        }
    }
}

// ---------------- launcher ----------------
extern "C" void kernel_launch(void* const* d_in, const int* in_sizes, int n_in,
                              void* d_out, int out_size) {
    const float* x      = (const float*)d_in[0];
    const float* edge   = (const float*)d_in[1];
    const float* cedge  = (const float*)d_in[2];
    const float* G      = (const float*)d_in[3];
    const float* CG     = (const float*)d_in[4];
    const float* W_emb  = (const float*)d_in[5];
    const float* b_emb  = (const float*)d_in[6];
    const float* W_q    = (const float*)d_in[7];
    const float* b_q    = (const float*)d_in[8];
    const float* W_k    = (const float*)d_in[9];
    const float* b_k    = (const float*)d_in[10];
    const float* W_eq   = (const float*)d_in[11];
    const float* b_eq   = (const float*)d_in[12];
    const float* W_ek   = (const float*)d_in[13];
    const float* b_ek   = (const float*)d_in[14];
    const float* W_ceq  = (const float*)d_in[15];
    const float* b_ceq  = (const float*)d_in[16];
    const float* W_cek  = (const float*)d_in[17];
    const float* b_cek  = (const float*)d_in[18];
    float* out = (float*)d_out;

    k_qk<<<Bsz * Nn, 64>>>(x, W_emb, b_emb, W_q, b_q, W_k, b_k);
    k_edge<<<2048, 256>>>(edge, cedge, W_eq, b_eq, W_ek, b_ek, W_ceq, b_ceq, W_cek, b_cek);
    k_gextra<<<256, 1024>>>(G, CG);
    k_attn<<<2048, 256>>>(out);
}

// round 10
// speedup vs baseline: 1.8123x; 1.0393x over previous
#include <cuda_runtime.h>
#include <cstdint>

#define Bsz 8
#define Nn 1024
#define Ee 256
#define Dm 64
#define Hh 4
#define DH 16

// fold 1/sqrt(64) * log2(e) into gq so scores feed ex2 directly
#define QSCALE 0.180336880520712f

// ---------------- device scratch (transposed layouts: [c][n]) ----------------
__device__ float d_qk[2][Bsz][Hh][DH][Nn];        // q, k  transposed
__device__ float d_e [4][Bsz][Hh][Ee][DH];        // eq, ek, ceq, cek
__device__ float d_g [2][2][Bsz][Hh][DH][Nn];     // [branch][q|k][b][h][c][n]

// ---------------- K1: fused prep (q/k projection + edge projections) ----------------
// grid 384 x 256 threads. bid<256: qk part (32 bn each). bid>=256: edge part.
__global__ void __launch_bounds__(256)
k_prep(const float* __restrict__ x,
       const float* __restrict__ W_emb, const float* __restrict__ b_emb,
       const float* __restrict__ W_q,   const float* __restrict__ b_q,
       const float* __restrict__ W_k,   const float* __restrict__ b_k,
       const float* __restrict__ edge,  const float* __restrict__ cedge,
       const float* __restrict__ W_eq,  const float* __restrict__ b_eq,
       const float* __restrict__ W_ek,  const float* __restrict__ b_ek,
       const float* __restrict__ W_ceq, const float* __restrict__ b_ceq,
       const float* __restrict__ W_cek, const float* __restrict__ b_cek) {
    __shared__ float pool[10880];                 // 43.5 KB, reused by both branches
    int tid = threadIdx.x;

    if (blockIdx.x < 256) {
        // ---------------- q/k projection: 32 bn per block ----------------
        float* sW   = pool;                       // [2][64][64] at 0 / 4096
        float* sWe0 = pool + 8448;                // 64
        float* sWe1 = pool + 8512;                // 64
        float* sbe  = pool + 8576;
        float* sbq  = pool + 8640;
        float* sbk  = pool + 8704;
        float* sx   = pool + 8768;                // 64 = 32 bn x 2
        float* semb = pool + 8832;                // [32][64]

        int gbn0 = blockIdx.x * 32;
        int b  = gbn0 >> 10;
        int n0 = gbn0 & 1023;

        for (int i = tid; i < 4096; i += 256) {
            sW[i]        = W_q[i];                // [j][c]
            sW[4096 + i] = W_k[i];
        }
        if (tid < 64) {
            sWe0[tid] = W_emb[tid];
            sWe1[tid] = W_emb[64 + tid];
            sbe[tid]  = b_emb[tid];
            sbq[tid]  = b_q[tid];
            sbk[tid]  = b_k[tid];
            sx[tid]   = x[gbn0 * 2 + tid];
        }
        __syncthreads();

        for (int i = tid; i < 2048; i += 256) {
            int bn = i >> 6, c = i & 63;
            semb[bn * 64 + c] = fmaf(sx[bn * 2], sWe0[c],
                                fmaf(sx[bn * 2 + 1], sWe1[c], sbe[c]));
        }
        __syncthreads();

        int c  = tid & 63;
        int bg = tid >> 6;                        // 4 groups x 8 bn
        float qa[8], ka[8];
#pragma unroll
        for (int it = 0; it < 8; ++it) { qa[it] = sbq[c]; ka[it] = sbk[c]; }
#pragma unroll
        for (int j = 0; j < 64; ++j) {
            float wq = sW[j * 64 + c];
            float wk = sW[4096 + j * 64 + c];
#pragma unroll
            for (int it = 0; it < 8; ++it) {
                float e = semb[(bg * 8 + it) * 64 + j];   // broadcast
                qa[it] = fmaf(e, wq, qa[it]);
                ka[it] = fmaf(e, wk, ka[it]);
            }
        }
        __syncthreads();
        // stage transposed: qs[c][bn], ks[c][bn], pad 33 (reuse sW region)
        float* qs = pool;                         // 64*33 = 2112
        float* ks = pool + 2112;
#pragma unroll
        for (int it = 0; it < 8; ++it) {
            int bn = bg * 8 + it;
            qs[c * 33 + bn] = qa[it];
            ks[c * 33 + bn] = ka[it];
        }
        __syncthreads();
        for (int i = tid; i < 2048; i += 256) {
            int cc = i >> 5, n = i & 31;
            int h = cc >> 4, c16 = cc & 15;
            d_qk[0][b][h][c16][n0 + n] = qs[cc * 33 + n];
            d_qk[1][b][h][c16][n0 + n] = ks[cc * 33 + n];
        }
    } else {
        // ---------------- edge projections: 256 row-jobs per block ----------------
        float* sW4 = pool;                        // [4][256]
        float* sb4 = pool + 1024;                 // [4][16]
        {
            const float* Ws[4] = {W_eq, W_ek, W_ceq, W_cek};
            for (int l = tid; l < 1024; l += 256)
                sW4[l] = Ws[l >> 8][l & 255];
            if (tid < 64) {
                const float* Bs[4] = {b_eq, b_ek, b_ceq, b_cek};
                sb4[tid] = Bs[tid >> 4][tid & 15];
            }
        }
        __syncthreads();

        int i = (blockIdx.x - 256) * 256 + tid;   // 0..32767
        int t = i >> 13;
        int r = i & 8191;
        const float* src = (t < 2 ? edge : cedge) + r * 16;
        float s[16];
#pragma unroll
        for (int j4 = 0; j4 < 4; ++j4) {
            float4 v = *(const float4*)(src + j4 * 4);
            s[j4 * 4 + 0] = v.x; s[j4 * 4 + 1] = v.y;
            s[j4 * 4 + 2] = v.z; s[j4 * 4 + 3] = v.w;
        }
        float acc[16];
#pragma unroll
        for (int cc = 0; cc < 16; ++cc) acc[cc] = sb4[t * 16 + cc];
#pragma unroll
        for (int j = 0; j < 16; ++j) {
            float sv = s[j];
#pragma unroll
            for (int cc = 0; cc < 16; ++cc)
                acc[cc] = fmaf(sv, sW4[t * 256 + j * 16 + cc], acc[cc]);
        }
        float* dst = (&d_e[0][0][0][0][0]) + (size_t)i * 16;
#pragma unroll
        for (int c4 = 0; c4 < 4; ++c4)
            *(float4*)(dst + c4 * 4) =
                make_float4(acc[c4 * 4], acc[c4 * 4 + 1], acc[c4 * 4 + 2], acc[c4 * 4 + 3]);
    }
}

// ---------------- K3: gq/gk (transposed out) + div, one pass over G ----------------
// grid: 2br * 8b * 16ntile = 256 blocks; 1024 threads = 16 c x 64 n
__global__ void __launch_bounds__(1024, 2)
k_gextra(const float* __restrict__ G, const float* __restrict__ CG) {
    int bid = blockIdx.x;
    int nt = bid & 15;  bid >>= 4;
    int b  = bid & 7;   bid >>= 3;
    int br = bid;
    int tid = threadIdx.x;
    int c    = tid >> 6;        // 0..15
    int nloc = tid & 63;        // 0..63
    int nbase = nt * 64;

    const float* Gm  = (br ? CG : G) + (size_t)b * Ee * Nn;
    const float* eqb = &d_e[br * 2 + 0][b][0][0][0];   // [h][e][c]
    const float* ekb = &d_e[br * 2 + 1][b][0][0][0];

    __shared__ float sg[16][64];
    __shared__ float seq[4][16][16];
    __shared__ float sek[4][16][16];

    float aq[4] = {0.f, 0.f, 0.f, 0.f};
    float ak[4] = {0.f, 0.f, 0.f, 0.f};
    float gsum = 0.f;

    for (int e0 = 0; e0 < Ee; e0 += 16) {
        __syncthreads();
        {
            int se = tid >> 6, sn = tid & 63;
            sg[se][sn] = Gm[(size_t)(e0 + se) * Nn + nbase + sn];
            int sh = tid >> 8, see = (tid >> 4) & 15, sc = tid & 15;
            seq[sh][see][sc] = eqb[(sh * Ee + e0 + see) * DH + sc];
            sek[sh][see][sc] = ekb[(sh * Ee + e0 + see) * DH + sc];
        }
        __syncthreads();
#pragma unroll
        for (int ee = 0; ee < 16; ++ee) {
            float g = sg[ee][nloc];
            gsum += g;
#pragma unroll
            for (int h = 0; h < 4; ++h) {
                aq[h] = fmaf(g, seq[h][ee][c], aq[h]);
                ak[h] = fmaf(g, sek[h][ee][c], ak[h]);
            }
        }
    }
    float rd = 1.0f / gsum;
    int n = nbase + nloc;
#pragma unroll
    for (int h = 0; h < 4; ++h) {
        float q = d_qk[0][b][h][c][n];
        float k = d_qk[1][b][h][c][n];
        d_g[br][0][b][h][c][n] = (q + aq[h] * rd) * QSCALE;   // 1/8 * log2(e)
        d_g[br][1][b][h][c][n] = (k + ak[h] * rd);
    }
}

// ---------------- K4: scores + softmax, K-in-registers (UNCHANGED, round-9 WIN) ----------------
#define RCHUNK 32
__global__ void __launch_bounds__(256, 2)
k_attn(float* __restrict__ out) {
    int bid = blockIdx.x;
    int chunk = bid & 31;  bid >>= 5;
    int h     = bid & 3;   bid >>= 2;
    int b     = bid & 7;   bid >>= 3;
    int br    = bid;
    int rbase = chunk * RCHUNK;

    const float* gq = &d_g[br][0][b][h][0][0];   // [c][n]
    const float* gk = &d_g[br][1][b][h][0][0];   // [c][n]

    __shared__ float sq[RCHUNK][20];
    __shared__ float spart[8][4];
    __shared__ float sinv[4];

    int tid  = threadIdx.x;
    int warp = tid >> 5, lane = tid & 31;
    int col0 = warp * 128 + lane * 4;

    float4 kk[16];
#pragma unroll
    for (int c = 0; c < 16; ++c)
        kk[c] = *(const float4*)(gk + c * Nn + col0);

    for (int i = tid; i < RCHUNK * 16; i += 256) {
        int c = i >> 5, r = i & 31;
        sq[r][c] = gq[c * Nn + rbase + r];
    }
    __syncthreads();

    size_t obase = ((((size_t)br * Bsz + b) * Hh + h) * Nn + rbase) * (size_t)Nn;

#pragma unroll 1
    for (int wv = 0; wv < RCHUNK / 4; ++wv) {
        int r0 = wv * 4;
        float4 ex[4];
        float part[4];
#pragma unroll
        for (int rr = 0; rr < 4; ++rr) {
            const float* qp = &sq[r0 + rr][0];
            float4 qa = *(const float4*)(qp + 0);
            float4 qb = *(const float4*)(qp + 4);
            float4 qc = *(const float4*)(qp + 8);
            float4 qd = *(const float4*)(qp + 12);
            float qv[16] = {qa.x, qa.y, qa.z, qa.w, qb.x, qb.y, qb.z, qb.w,
                            qc.x, qc.y, qc.z, qc.w, qd.x, qd.y, qd.z, qd.w};
            float s0 = 0.f, s1 = 0.f, s2 = 0.f, s3 = 0.f;
#pragma unroll
            for (int c = 0; c < 16; ++c) {
                s0 = fmaf(qv[c], kk[c].x, s0);
                s1 = fmaf(qv[c], kk[c].y, s1);
                s2 = fmaf(qv[c], kk[c].z, s2);
                s3 = fmaf(qv[c], kk[c].w, s3);
            }
            float e0, e1, e2, e3;
            asm("ex2.approx.f32 %0, %1;" : "=f"(e0) : "f"(s0));
            asm("ex2.approx.f32 %0, %1;" : "=f"(e1) : "f"(s1));
            asm("ex2.approx.f32 %0, %1;" : "=f"(e2) : "f"(s2));
            asm("ex2.approx.f32 %0, %1;" : "=f"(e3) : "f"(s3));
            ex[rr] = make_float4(e0, e1, e2, e3);
            part[rr] = (e0 + e1) + (e2 + e3);
        }
#pragma unroll
        for (int o = 16; o; o >>= 1)
#pragma unroll
            for (int rr = 0; rr < 4; ++rr)
                part[rr] += __shfl_xor_sync(0xffffffffu, part[rr], o);
        if (lane == 0) {
#pragma unroll
            for (int rr = 0; rr < 4; ++rr) spart[warp][rr] = part[rr];
        }
        __syncthreads();
        if (tid < 4) {
            float s = 0.f;
#pragma unroll
            for (int w = 0; w < 8; ++w) s += spart[w][tid];
            sinv[tid] = 1.0f / s;
        }
        __syncthreads();
#pragma unroll
        for (int rr = 0; rr < 4; ++rr) {
            float iv = sinv[rr];
            float4 v = ex[rr];
            v.x *= iv; v.y *= iv; v.z *= iv; v.w *= iv;
            *(float4*)(out + obase + (size_t)(r0 + rr) * Nn + col0) = v;
        }
    }
}

// ---------------- launcher ----------------
extern "C" void kernel_launch(void* const* d_in, const int* in_sizes, int n_in,
                              void* d_out, int out_size) {
    const float* x      = (const float*)d_in[0];
    const float* edge   = (const float*)d_in[1];
    const float* cedge  = (const float*)d_in[2];
    const float* G      = (const float*)d_in[3];
    const float* CG     = (const float*)d_in[4];
    const float* W_emb  = (const float*)d_in[5];
    const float* b_emb  = (const float*)d_in[6];
    const float* W_q    = (const float*)d_in[7];
    const float* b_q    = (const float*)d_in[8];
    const float* W_k    = (const float*)d_in[9];
    const float* b_k    = (const float*)d_in[10];
    const float* W_eq   = (const float*)d_in[11];
    const float* b_eq   = (const float*)d_in[12];
    const float* W_ek   = (const float*)d_in[13];
    const float* b_ek   = (const float*)d_in[14];
    const float* W_ceq  = (const float*)d_in[15];
    const float* b_ceq  = (const float*)d_in[16];
    const float* W_cek  = (const float*)d_in[17];
    const float* b_cek  = (const float*)d_in[18];
    float* out = (float*)d_out;

    k_prep<<<384, 256>>>(x, W_emb, b_emb, W_q, b_q, W_k, b_k,
                         edge, cedge, W_eq, b_eq, W_ek, b_ek,
                         W_ceq, b_ceq, W_cek, b_cek);
    k_gextra<<<256, 1024>>>(G, CG);
    k_attn<<<2048, 256>>>(out);
}

// round 12
// speedup vs baseline: 2.4320x; 1.3419x over previous
#include <cuda_runtime.h>
#include <cstdint>

#define Bsz 8
#define Nn 1024
#define Ee 256
#define Dm 64
#define Hh 4
#define DH 16

// fold 1/sqrt(64) * log2(e) into gq so scores feed ex2 directly
#define QSCALE 0.180336880520712f

// ---------------- device scratch (transposed layouts: [c][n]) ----------------
__device__ float d_qk[2][Bsz][Hh][DH][Nn];        // q, k  transposed
__device__ float d_e [4][Bsz][Hh][Ee][DH];        // eq, ek, ceq, cek
__device__ float d_g [2][2][Bsz][Hh][DH][Nn];     // [branch][q|k][b][h][c][n]

// ---------------- K1: fused prep (q/k projection + edge projections) ----------------
// grid 384 x 256 threads. bid<256: qk part (32 bn each). bid>=256: edge part.
__global__ void __launch_bounds__(256)
k_prep(const float* __restrict__ x,
       const float* __restrict__ W_emb, const float* __restrict__ b_emb,
       const float* __restrict__ W_q,   const float* __restrict__ b_q,
       const float* __restrict__ W_k,   const float* __restrict__ b_k,
       const float* __restrict__ edge,  const float* __restrict__ cedge,
       const float* __restrict__ W_eq,  const float* __restrict__ b_eq,
       const float* __restrict__ W_ek,  const float* __restrict__ b_ek,
       const float* __restrict__ W_ceq, const float* __restrict__ b_ceq,
       const float* __restrict__ W_cek, const float* __restrict__ b_cek) {
    __shared__ float pool[10880];                 // 43.5 KB, reused by both branches
    int tid = threadIdx.x;

    if (blockIdx.x < 256) {
        // ---------------- q/k projection: 32 bn per block ----------------
        float* sW   = pool;                       // [2][64][64] at 0 / 4096
        float* sWe0 = pool + 8448;                // 64
        float* sWe1 = pool + 8512;                // 64
        float* sbe  = pool + 8576;
        float* sbq  = pool + 8640;
        float* sbk  = pool + 8704;
        float* sx   = pool + 8768;                // 64 = 32 bn x 2
        float* semb = pool + 8832;                // [32][64]

        int gbn0 = blockIdx.x * 32;
        int b  = gbn0 >> 10;
        int n0 = gbn0 & 1023;

        for (int i = tid; i < 4096; i += 256) {
            sW[i]        = W_q[i];                // [j][c]
            sW[4096 + i] = W_k[i];
        }
        if (tid < 64) {
            sWe0[tid] = W_emb[tid];
            sWe1[tid] = W_emb[64 + tid];
            sbe[tid]  = b_emb[tid];
            sbq[tid]  = b_q[tid];
            sbk[tid]  = b_k[tid];
            sx[tid]   = x[gbn0 * 2 + tid];
        }
        __syncthreads();

        for (int i = tid; i < 2048; i += 256) {
            int bn = i >> 6, c = i & 63;
            semb[bn * 64 + c] = fmaf(sx[bn * 2], sWe0[c],
                                fmaf(sx[bn * 2 + 1], sWe1[c], sbe[c]));
        }
        __syncthreads();

        int c  = tid & 63;
        int bg = tid >> 6;                        // 4 groups x 8 bn
        float qa[8], ka[8];
#pragma unroll
        for (int it = 0; it < 8; ++it) { qa[it] = sbq[c]; ka[it] = sbk[c]; }
#pragma unroll
        for (int j = 0; j < 64; ++j) {
            float wq = sW[j * 64 + c];
            float wk = sW[4096 + j * 64 + c];
#pragma unroll
            for (int it = 0; it < 8; ++it) {
                float e = semb[(bg * 8 + it) * 64 + j];   // broadcast
                qa[it] = fmaf(e, wq, qa[it]);
                ka[it] = fmaf(e, wk, ka[it]);
            }
        }
        __syncthreads();
        // stage transposed: qs[c][bn], ks[c][bn], pad 33 (reuse sW region)
        float* qs = pool;                         // 64*33 = 2112
        float* ks = pool + 2112;
#pragma unroll
        for (int it = 0; it < 8; ++it) {
            int bn = bg * 8 + it;
            qs[c * 33 + bn] = qa[it];
            ks[c * 33 + bn] = ka[it];
        }
        __syncthreads();
        for (int i = tid; i < 2048; i += 256) {
            int cc = i >> 5, n = i & 31;
            int h = cc >> 4, c16 = cc & 15;
            d_qk[0][b][h][c16][n0 + n] = qs[cc * 33 + n];
            d_qk[1][b][h][c16][n0 + n] = ks[cc * 33 + n];
        }
    } else {
        // ---------------- edge projections: 256 row-jobs per block ----------------
        float* sW4 = pool;                        // [4][256]
        float* sb4 = pool + 1024;                 // [4][16]
        {
            const float* Ws[4] = {W_eq, W_ek, W_ceq, W_cek};
            for (int l = tid; l < 1024; l += 256)
                sW4[l] = Ws[l >> 8][l & 255];
            if (tid < 64) {
                const float* Bs[4] = {b_eq, b_ek, b_ceq, b_cek};
                sb4[tid] = Bs[tid >> 4][tid & 15];
            }
        }
        __syncthreads();

        int i = (blockIdx.x - 256) * 256 + tid;   // 0..32767
        int t = i >> 13;
        int r = i & 8191;
        const float* src = (t < 2 ? edge : cedge) + r * 16;
        float s[16];
#pragma unroll
        for (int j4 = 0; j4 < 4; ++j4) {
            float4 v = *(const float4*)(src + j4 * 4);
            s[j4 * 4 + 0] = v.x; s[j4 * 4 + 1] = v.y;
            s[j4 * 4 + 2] = v.z; s[j4 * 4 + 3] = v.w;
        }
        float acc[16];
#pragma unroll
        for (int cc = 0; cc < 16; ++cc) acc[cc] = sb4[t * 16 + cc];
#pragma unroll
        for (int j = 0; j < 16; ++j) {
            float sv = s[j];
#pragma unroll
            for (int cc = 0; cc < 16; ++cc)
                acc[cc] = fmaf(sv, sW4[t * 256 + j * 16 + cc], acc[cc]);
        }
        float* dst = (&d_e[0][0][0][0][0]) + (size_t)i * 16;
#pragma unroll
        for (int c4 = 0; c4 < 4; ++c4)
            *(float4*)(dst + c4 * 4) =
                make_float4(acc[c4 * 4], acc[c4 * 4 + 1], acc[c4 * 4 + 2], acc[c4 * 4 + 3]);
    }
}

// ---------------- K3 v2: gq/gk + div — 4 n per thread, float4 everywhere ----------------
// grid: 2br * 8b * 16nt = 256 blocks; 256 threads = 16 c x 16 ns (4 n each).
// Per e-step: 1 LDS.128 (G) + 8 broadcast LDS (e-proj) + 36 FFMA.
__global__ void __launch_bounds__(256, 2)
k_gextra(const float* __restrict__ G, const float* __restrict__ CG) {
    int bid = blockIdx.x;
    int nt = bid & 15;  bid >>= 4;
    int b  = bid & 7;   bid >>= 3;
    int br = bid;
    int tid = threadIdx.x;
    int c  = tid >> 4;          // 0..15
    int ns = tid & 15;          // 0..15 -> n = nbase + ns*4 + 0..3
    int nbase = nt * 64;

    const float* Gm  = (br ? CG : G) + (size_t)b * Ee * Nn;
    const float* eqb = &d_e[br * 2 + 0][b][0][0][0];   // [h][e][c], h-stride 4096
    const float* ekb = &d_e[br * 2 + 1][b][0][0][0];

    __shared__ float4 sg4[16][16];       // [ee][ns]
    __shared__ float  seq[4][16][16];    // [h][ee][c]  = 1024 floats = 256 float4
    __shared__ float  sek[4][16][16];

    float aq[4][4], ak[4][4];            // [h][n]
#pragma unroll
    for (int h = 0; h < 4; ++h)
#pragma unroll
        for (int j = 0; j < 4; ++j) { aq[h][j] = 0.f; ak[h][j] = 0.f; }
    float gs0 = 0.f, gs1 = 0.f, gs2 = 0.f, gs3 = 0.f;

    for (int e0 = 0; e0 < Ee; e0 += 16) {
        __syncthreads();
        {
            // G tile: 16 e-rows x 64 n = 256 float4, one per thread
            int ge = tid >> 4, gn = tid & 15;
            sg4[ge][gn] = *(const float4*)(Gm + (size_t)(e0 + ge) * Nn + nbase + gn * 4);
            // e-proj tiles: each is 4h x 16ee x 16c = 256 float4; one per thread per array.
            // flat float4 index tid: h = tid>>6, ee = (tid&63)>>2, c4 = tid&3
            float4* sq4 = (float4*)&seq[0][0][0];
            float4* sk4 = (float4*)&sek[0][0][0];
            int h4 = tid >> 6, ee4 = (tid & 63) >> 2, c4 = tid & 3;
            size_t goff = (size_t)(h4 * Ee + e0 + ee4) * DH + c4 * 4;
            sq4[tid] = *(const float4*)(eqb + goff);
            sk4[tid] = *(const float4*)(ekb + goff);
        }
        __syncthreads();
#pragma unroll
        for (int ee = 0; ee < 16; ++ee) {
            float4 g = sg4[ee][ns];
            gs0 += g.x; gs1 += g.y; gs2 += g.z; gs3 += g.w;
#pragma unroll
            for (int h = 0; h < 4; ++h) {
                float eqv = seq[h][ee][c];
                float ekv = sek[h][ee][c];
                aq[h][0] = fmaf(g.x, eqv, aq[h][0]);
                aq[h][1] = fmaf(g.y, eqv, aq[h][1]);
                aq[h][2] = fmaf(g.z, eqv, aq[h][2]);
                aq[h][3] = fmaf(g.w, eqv, aq[h][3]);
                ak[h][0] = fmaf(g.x, ekv, ak[h][0]);
                ak[h][1] = fmaf(g.y, ekv, ak[h][1]);
                ak[h][2] = fmaf(g.z, ekv, ak[h][2]);
                ak[h][3] = fmaf(g.w, ekv, ak[h][3]);
            }
        }
    }
    float rd0 = 1.0f / gs0, rd1 = 1.0f / gs1, rd2 = 1.0f / gs2, rd3 = 1.0f / gs3;
    int n0 = nbase + ns * 4;
#pragma unroll
    for (int h = 0; h < 4; ++h) {
        float4 q = *(const float4*)&d_qk[0][b][h][c][n0];
        float4 k = *(const float4*)&d_qk[1][b][h][c][n0];
        float4 oq, ok;
        oq.x = (q.x + aq[h][0] * rd0) * QSCALE;
        oq.y = (q.y + aq[h][1] * rd1) * QSCALE;
        oq.z = (q.z + aq[h][2] * rd2) * QSCALE;
        oq.w = (q.w + aq[h][3] * rd3) * QSCALE;
        ok.x = (k.x + ak[h][0] * rd0);
        ok.y = (k.y + ak[h][1] * rd1);
        ok.z = (k.z + ak[h][2] * rd2);
        ok.w = (k.w + ak[h][3] * rd3);
        *(float4*)&d_g[br][0][b][h][c][n0] = oq;
        *(float4*)&d_g[br][1][b][h][c][n0] = ok;
    }
}

// ---------------- K4: scores + softmax, K-in-registers (UNCHANGED, round-9 WIN) ----------------
#define RCHUNK 32
__global__ void __launch_bounds__(256, 2)
k_attn(float* __restrict__ out) {
    int bid = blockIdx.x;
    int chunk = bid & 31;  bid >>= 5;
    int h     = bid & 3;   bid >>= 2;
    int b     = bid & 7;   bid >>= 3;
    int br    = bid;
    int rbase = chunk * RCHUNK;

    const float* gq = &d_g[br][0][b][h][0][0];   // [c][n]
    const float* gk = &d_g[br][1][b][h][0][0];   // [c][n]

    __shared__ float sq[RCHUNK][20];
    __shared__ float spart[8][4];
    __shared__ float sinv[4];

    int tid  = threadIdx.x;
    int warp = tid >> 5, lane = tid & 31;
    int col0 = warp * 128 + lane * 4;

    float4 kk[16];
#pragma unroll
    for (int c = 0; c < 16; ++c)
        kk[c] = *(const float4*)(gk + c * Nn + col0);

    for (int i = tid; i < RCHUNK * 16; i += 256) {
        int c = i >> 5, r = i & 31;
        sq[r][c] = gq[c * Nn + rbase + r];
    }
    __syncthreads();

    size_t obase = ((((size_t)br * Bsz + b) * Hh + h) * Nn + rbase) * (size_t)Nn;

#pragma unroll 1
    for (int wv = 0; wv < RCHUNK / 4; ++wv) {
        int r0 = wv * 4;
        float4 ex[4];
        float part[4];
#pragma unroll
        for (int rr = 0; rr < 4; ++rr) {
            const float* qp = &sq[r0 + rr][0];
            float4 qa = *(const float4*)(qp + 0);
            float4 qb = *(const float4*)(qp + 4);
            float4 qc = *(const float4*)(qp + 8);
            float4 qd = *(const float4*)(qp + 12);
            float qv[16] = {qa.x, qa.y, qa.z, qa.w, qb.x, qb.y, qb.z, qb.w,
                            qc.x, qc.y, qc.z, qc.w, qd.x, qd.y, qd.z, qd.w};
            float s0 = 0.f, s1 = 0.f, s2 = 0.f, s3 = 0.f;
#pragma unroll
            for (int c = 0; c < 16; ++c) {
                s0 = fmaf(qv[c], kk[c].x, s0);
                s1 = fmaf(qv[c], kk[c].y, s1);
                s2 = fmaf(qv[c], kk[c].z, s2);
                s3 = fmaf(qv[c], kk[c].w, s3);
            }
            float e0, e1, e2, e3;
            asm("ex2.approx.f32 %0, %1;" : "=f"(e0) : "f"(s0));
            asm("ex2.approx.f32 %0, %1;" : "=f"(e1) : "f"(s1));
            asm("ex2.approx.f32 %0, %1;" : "=f"(e2) : "f"(s2));
            asm("ex2.approx.f32 %0, %1;" : "=f"(e3) : "f"(s3));
            ex[rr] = make_float4(e0, e1, e2, e3);
            part[rr] = (e0 + e1) + (e2 + e3);
        }
#pragma unroll
        for (int o = 16; o; o >>= 1)
#pragma unroll
            for (int rr = 0; rr < 4; ++rr)
                part[rr] += __shfl_xor_sync(0xffffffffu, part[rr], o);
        if (lane == 0) {
#pragma unroll
            for (int rr = 0; rr < 4; ++rr) spart[warp][rr] = part[rr];
        }
        __syncthreads();
        if (tid < 4) {
            float s = 0.f;
#pragma unroll
            for (int w = 0; w < 8; ++w) s += spart[w][tid];
            sinv[tid] = 1.0f / s;
        }
        __syncthreads();
#pragma unroll
        for (int rr = 0; rr < 4; ++rr) {
            float iv = sinv[rr];
            float4 v = ex[rr];
            v.x *= iv; v.y *= iv; v.z *= iv; v.w *= iv;
            *(float4*)(out + obase + (size_t)(r0 + rr) * Nn + col0) = v;
        }
    }
}

// ---------------- launcher ----------------
extern "C" void kernel_launch(void* const* d_in, const int* in_sizes, int n_in,
                              void* d_out, int out_size) {
    const float* x      = (const float*)d_in[0];
    const float* edge   = (const float*)d_in[1];
    const float* cedge  = (const float*)d_in[2];
    const float* G      = (const float*)d_in[3];
    const float* CG     = (const float*)d_in[4];
    const float* W_emb  = (const float*)d_in[5];
    const float* b_emb  = (const float*)d_in[6];
    const float* W_q    = (const float*)d_in[7];
    const float* b_q    = (const float*)d_in[8];
    const float* W_k    = (const float*)d_in[9];
    const float* b_k    = (const float*)d_in[10];
    const float* W_eq   = (const float*)d_in[11];
    const float* b_eq   = (const float*)d_in[12];
    const float* W_ek   = (const float*)d_in[13];
    const float* b_ek   = (const float*)d_in[14];
    const float* W_ceq  = (const float*)d_in[15];
    const float* b_ceq  = (const float*)d_in[16];
    const float* W_cek  = (const float*)d_in[17];
    const float* b_cek  = (const float*)d_in[18];
    float* out = (float*)d_out;

    k_prep<<<384, 256>>>(x, W_emb, b_emb, W_q, b_q, W_k, b_k,
                         edge, cedge, W_eq, b_eq, W_ek, b_ek,
                         W_ceq, b_ceq, W_cek, b_cek);
    k_gextra<<<256, 256>>>(G, CG);
    k_attn<<<2048, 256>>>(out);
}

// round 13
// speedup vs baseline: 2.5505x; 1.0487x over previous
#include <cuda_runtime.h>
#include <cstdint>

#define Bsz 8
#define Nn 1024
#define Ee 256
#define Dm 64
#define Hh 4
#define DH 16

// fold 1/sqrt(64) * log2(e) into gq so scores feed ex2 directly
#define QSCALE 0.180336880520712f

// ---------------- device scratch (transposed layouts: [c][n]) ----------------
__device__ float d_qk[2][Bsz][Hh][DH][Nn];        // q, k  transposed
__device__ float d_e [4][Bsz][Hh][Ee][DH];        // eq, ek, ceq, cek
__device__ float d_g [2][2][Bsz][Hh][DH][Nn];     // [branch][q|k][b][h][c][n]

// ---------------- K1: fused prep (q/k projection + edge projections) ----------------
// grid 384 x 256 threads. bid<256: qk part (32 bn each). bid>=256: edge part.
__global__ void __launch_bounds__(256)
k_prep(const float* __restrict__ x,
       const float* __restrict__ W_emb, const float* __restrict__ b_emb,
       const float* __restrict__ W_q,   const float* __restrict__ b_q,
       const float* __restrict__ W_k,   const float* __restrict__ b_k,
       const float* __restrict__ edge,  const float* __restrict__ cedge,
       const float* __restrict__ W_eq,  const float* __restrict__ b_eq,
       const float* __restrict__ W_ek,  const float* __restrict__ b_ek,
       const float* __restrict__ W_ceq, const float* __restrict__ b_ceq,
       const float* __restrict__ W_cek, const float* __restrict__ b_cek) {
    __shared__ float pool[10880];                 // 43.5 KB, reused by both branches
    int tid = threadIdx.x;

    if (blockIdx.x < 256) {
        // ---------------- q/k projection: 32 bn per block ----------------
        float* sW   = pool;                       // [2][64][64] at 0 / 4096
        float* sWe0 = pool + 8448;                // 64
        float* sWe1 = pool + 8512;                // 64
        float* sbe  = pool + 8576;
        float* sbq  = pool + 8640;
        float* sbk  = pool + 8704;
        float* sx   = pool + 8768;                // 64 = 32 bn x 2
        float* semb = pool + 8832;                // [32][64]

        int gbn0 = blockIdx.x * 32;
        int b  = gbn0 >> 10;
        int n0 = gbn0 & 1023;

        for (int i = tid; i < 4096; i += 256) {
            sW[i]        = W_q[i];                // [j][c]
            sW[4096 + i] = W_k[i];
        }
        if (tid < 64) {
            sWe0[tid] = W_emb[tid];
            sWe1[tid] = W_emb[64 + tid];
            sbe[tid]  = b_emb[tid];
            sbq[tid]  = b_q[tid];
            sbk[tid]  = b_k[tid];
            sx[tid]   = x[gbn0 * 2 + tid];
        }
        __syncthreads();

        for (int i = tid; i < 2048; i += 256) {
            int bn = i >> 6, c = i & 63;
            semb[bn * 64 + c] = fmaf(sx[bn * 2], sWe0[c],
                                fmaf(sx[bn * 2 + 1], sWe1[c], sbe[c]));
        }
        __syncthreads();

        int c  = tid & 63;
        int bg = tid >> 6;                        // 4 groups x 8 bn
        float qa[8], ka[8];
#pragma unroll
        for (int it = 0; it < 8; ++it) { qa[it] = sbq[c]; ka[it] = sbk[c]; }
#pragma unroll
        for (int j = 0; j < 64; ++j) {
            float wq = sW[j * 64 + c];
            float wk = sW[4096 + j * 64 + c];
#pragma unroll
            for (int it = 0; it < 8; ++it) {
                float e = semb[(bg * 8 + it) * 64 + j];   // broadcast
                qa[it] = fmaf(e, wq, qa[it]);
                ka[it] = fmaf(e, wk, ka[it]);
            }
        }
        __syncthreads();
        // stage transposed: qs[c][bn], ks[c][bn], pad 33 (reuse sW region)
        float* qs = pool;                         // 64*33 = 2112
        float* ks = pool + 2112;
#pragma unroll
        for (int it = 0; it < 8; ++it) {
            int bn = bg * 8 + it;
            qs[c * 33 + bn] = qa[it];
            ks[c * 33 + bn] = ka[it];
        }
        __syncthreads();
        for (int i = tid; i < 2048; i += 256) {
            int cc = i >> 5, n = i & 31;
            int h = cc >> 4, c16 = cc & 15;
            d_qk[0][b][h][c16][n0 + n] = qs[cc * 33 + n];
            d_qk[1][b][h][c16][n0 + n] = ks[cc * 33 + n];
        }
    } else {
        // ---------------- edge projections: 256 row-jobs per block ----------------
        float* sW4 = pool;                        // [4][256]
        float* sb4 = pool + 1024;                 // [4][16]
        {
            const float* Ws[4] = {W_eq, W_ek, W_ceq, W_cek};
            for (int l = tid; l < 1024; l += 256)
                sW4[l] = Ws[l >> 8][l & 255];
            if (tid < 64) {
                const float* Bs[4] = {b_eq, b_ek, b_ceq, b_cek};
                sb4[tid] = Bs[tid >> 4][tid & 15];
            }
        }
        __syncthreads();

        int i = (blockIdx.x - 256) * 256 + tid;   // 0..32767
        int t = i >> 13;
        int r = i & 8191;
        const float* src = (t < 2 ? edge : cedge) + r * 16;
        float s[16];
#pragma unroll
        for (int j4 = 0; j4 < 4; ++j4) {
            float4 v = *(const float4*)(src + j4 * 4);
            s[j4 * 4 + 0] = v.x; s[j4 * 4 + 1] = v.y;
            s[j4 * 4 + 2] = v.z; s[j4 * 4 + 3] = v.w;
        }
        float acc[16];
#pragma unroll
        for (int cc = 0; cc < 16; ++cc) acc[cc] = sb4[t * 16 + cc];
#pragma unroll
        for (int j = 0; j < 16; ++j) {
            float sv = s[j];
#pragma unroll
            for (int cc = 0; cc < 16; ++cc)
                acc[cc] = fmaf(sv, sW4[t * 256 + j * 16 + cc], acc[cc]);
        }
        float* dst = (&d_e[0][0][0][0][0]) + (size_t)i * 16;
#pragma unroll
        for (int c4 = 0; c4 < 4; ++c4)
            *(float4*)(dst + c4 * 4) =
                make_float4(acc[c4 * 4], acc[c4 * 4 + 1], acc[c4 * 4 + 2], acc[c4 * 4 + 3]);
    }
}

// ---------------- K3 v3: gq/gk + div — float4 tiling + register prefetch ----------------
// grid: 2br * 8b * 16nt = 256 blocks; 256 threads = 16 c x 16 ns (4 n each).
__global__ void __launch_bounds__(256, 2)
k_gextra(const float* __restrict__ G, const float* __restrict__ CG) {
    int bid = blockIdx.x;
    int nt = bid & 15;  bid >>= 4;
    int b  = bid & 7;   bid >>= 3;
    int br = bid;
    int tid = threadIdx.x;
    int c  = tid >> 4;          // 0..15
    int ns = tid & 15;          // 0..15 -> n = nbase + ns*4 + 0..3
    int nbase = nt * 64;

    const float* Gm  = (br ? CG : G) + (size_t)b * Ee * Nn;
    const float* eqb = &d_e[br * 2 + 0][b][0][0][0];   // [h][e][c], h-stride 4096
    const float* ekb = &d_e[br * 2 + 1][b][0][0][0];

    __shared__ float4 sg4[16][16];       // [ee][ns]
    __shared__ float  seq[4][16][16];    // [h][ee][c]  = 256 float4
    __shared__ float  sek[4][16][16];
    float4* sq4 = (float4*)&seq[0][0][0];
    float4* sk4 = (float4*)&sek[0][0][0];

    // staging index split (one float4 per thread per array per tile)
    int ge = tid >> 4, gn = tid & 15;
    int h4 = tid >> 6, ee4 = (tid & 63) >> 2, c4 = tid & 3;
    const float* gsrc = Gm + (size_t)ge * Nn + nbase + gn * 4;
    size_t eoff = (size_t)(h4 * Ee + ee4) * DH + c4 * 4;

    float aq[4][4], ak[4][4];            // [h][n]
#pragma unroll
    for (int h = 0; h < 4; ++h)
#pragma unroll
        for (int j = 0; j < 4; ++j) { aq[h][j] = 0.f; ak[h][j] = 0.f; }
    float gs0 = 0.f, gs1 = 0.f, gs2 = 0.f, gs3 = 0.f;

    // preload tile 0
    float4 gpre = *(const float4*)(gsrc);
    float4 qpre = *(const float4*)(eqb + eoff);
    float4 kpre = *(const float4*)(ekb + eoff);

#pragma unroll 1
    for (int e0 = 0; e0 < Ee; e0 += 16) {
        sg4[ge][gn] = gpre;
        sq4[tid] = qpre;
        sk4[tid] = kpre;
        __syncthreads();
        if (e0 + 16 < Ee) {              // prefetch next tile (overlaps compute)
            gpre = *(const float4*)(gsrc + (size_t)(e0 + 16) * Nn);
            qpre = *(const float4*)(eqb + eoff + (size_t)(e0 + 16) * DH);
            kpre = *(const float4*)(ekb + eoff + (size_t)(e0 + 16) * DH);
        }
#pragma unroll
        for (int ee = 0; ee < 16; ++ee) {
            float4 g = sg4[ee][ns];
            gs0 += g.x; gs1 += g.y; gs2 += g.z; gs3 += g.w;
#pragma unroll
            for (int h = 0; h < 4; ++h) {
                float eqv = seq[h][ee][c];
                float ekv = sek[h][ee][c];
                aq[h][0] = fmaf(g.x, eqv, aq[h][0]);
                aq[h][1] = fmaf(g.y, eqv, aq[h][1]);
                aq[h][2] = fmaf(g.z, eqv, aq[h][2]);
                aq[h][3] = fmaf(g.w, eqv, aq[h][3]);
                ak[h][0] = fmaf(g.x, ekv, ak[h][0]);
                ak[h][1] = fmaf(g.y, ekv, ak[h][1]);
                ak[h][2] = fmaf(g.z, ekv, ak[h][2]);
                ak[h][3] = fmaf(g.w, ekv, ak[h][3]);
            }
        }
        __syncthreads();
    }
    float rd0 = 1.0f / gs0, rd1 = 1.0f / gs1, rd2 = 1.0f / gs2, rd3 = 1.0f / gs3;
    int n0 = nbase + ns * 4;
#pragma unroll
    for (int h = 0; h < 4; ++h) {
        float4 q = *(const float4*)&d_qk[0][b][h][c][n0];
        float4 k = *(const float4*)&d_qk[1][b][h][c][n0];
        float4 oq, ok;
        oq.x = (q.x + aq[h][0] * rd0) * QSCALE;
        oq.y = (q.y + aq[h][1] * rd1) * QSCALE;
        oq.z = (q.z + aq[h][2] * rd2) * QSCALE;
        oq.w = (q.w + aq[h][3] * rd3) * QSCALE;
        ok.x = (k.x + ak[h][0] * rd0);
        ok.y = (k.y + ak[h][1] * rd1);
        ok.z = (k.z + ak[h][2] * rd2);
        ok.w = (k.w + ak[h][3] * rd3);
        *(float4*)&d_g[br][0][b][h][c][n0] = oq;
        *(float4*)&d_g[br][1][b][h][c][n0] = ok;
    }
}

// ---------------- K4 v2: scores + softmax — ONE barrier/wave + streaming stores ----------------
#define RCHUNK 32
__global__ void __launch_bounds__(256, 2)
k_attn(float* __restrict__ out) {
    int bid = blockIdx.x;
    int chunk = bid & 31;  bid >>= 5;
    int h     = bid & 3;   bid >>= 2;
    int b     = bid & 7;   bid >>= 3;
    int br    = bid;
    int rbase = chunk * RCHUNK;

    const float* gq = &d_g[br][0][b][h][0][0];   // [c][n]
    const float* gk = &d_g[br][1][b][h][0][0];   // [c][n]

    __shared__ float sq[RCHUNK][20];
    __shared__ float spart[2][8][4];             // parity double-buffered

    int tid  = threadIdx.x;
    int warp = tid >> 5, lane = tid & 31;
    int col0 = warp * 128 + lane * 4;

    float4 kk[16];
#pragma unroll
    for (int c = 0; c < 16; ++c)
        kk[c] = *(const float4*)(gk + c * Nn + col0);

    for (int i = tid; i < RCHUNK * 16; i += 256) {
        int c = i >> 5, r = i & 31;
        sq[r][c] = gq[c * Nn + rbase + r];
    }
    __syncthreads();

    size_t obase = ((((size_t)br * Bsz + b) * Hh + h) * Nn + rbase) * (size_t)Nn;

#pragma unroll 1
    for (int wv = 0; wv < RCHUNK / 4; ++wv) {
        int r0 = wv * 4;
        float4 ex[4];
        float part[4];
#pragma unroll
        for (int rr = 0; rr < 4; ++rr) {
            const float* qp = &sq[r0 + rr][0];
            float4 qa = *(const float4*)(qp + 0);
            float4 qb = *(const float4*)(qp + 4);
            float4 qc = *(const float4*)(qp + 8);
            float4 qd = *(const float4*)(qp + 12);
            float qv[16] = {qa.x, qa.y, qa.z, qa.w, qb.x, qb.y, qb.z, qb.w,
                            qc.x, qc.y, qc.z, qc.w, qd.x, qd.y, qd.z, qd.w};
            float s0 = 0.f, s1 = 0.f, s2 = 0.f, s3 = 0.f;
#pragma unroll
            for (int c = 0; c < 16; ++c) {
                s0 = fmaf(qv[c], kk[c].x, s0);
                s1 = fmaf(qv[c], kk[c].y, s1);
                s2 = fmaf(qv[c], kk[c].z, s2);
                s3 = fmaf(qv[c], kk[c].w, s3);
            }
            float e0, e1, e2, e3;
            asm("ex2.approx.f32 %0, %1;" : "=f"(e0) : "f"(s0));
            asm("ex2.approx.f32 %0, %1;" : "=f"(e1) : "f"(s1));
            asm("ex2.approx.f32 %0, %1;" : "=f"(e2) : "f"(s2));
            asm("ex2.approx.f32 %0, %1;" : "=f"(e3) : "f"(s3));
            ex[rr] = make_float4(e0, e1, e2, e3);
            part[rr] = (e0 + e1) + (e2 + e3);
        }
#pragma unroll
        for (int o = 16; o; o >>= 1)
#pragma unroll
            for (int rr = 0; rr < 4; ++rr)
                part[rr] += __shfl_xor_sync(0xffffffffu, part[rr], o);
        int par = wv & 1;
        if (lane == 0) {
#pragma unroll
            for (int rr = 0; rr < 4; ++rr) spart[par][warp][rr] = part[rr];
        }
        __syncthreads();                         // single barrier per wave
#pragma unroll
        for (int rr = 0; rr < 4; ++rr) {
            float v = spart[par][lane & 7][rr];  // 8-way broadcast LDS
            v += __shfl_xor_sync(0xffffffffu, v, 1);
            v += __shfl_xor_sync(0xffffffffu, v, 2);
            v += __shfl_xor_sync(0xffffffffu, v, 4);
            float iv = 1.0f / v;
            float4 o4 = ex[rr];
            o4.x *= iv; o4.y *= iv; o4.z *= iv; o4.w *= iv;
            __stcs((float4*)(out + obase + (size_t)(r0 + rr) * Nn + col0), o4);
        }
    }
}

// ---------------- launcher ----------------
extern "C" void kernel_launch(void* const* d_in, const int* in_sizes, int n_in,
                              void* d_out, int out_size) {
    const float* x      = (const float*)d_in[0];
    const float* edge   = (const float*)d_in[1];
    const float* cedge  = (const float*)d_in[2];
    const float* G      = (const float*)d_in[3];
    const float* CG     = (const float*)d_in[4];
    const float* W_emb  = (const float*)d_in[5];
    const float* b_emb  = (const float*)d_in[6];
    const float* W_q    = (const float*)d_in[7];
    const float* b_q    = (const float*)d_in[8];
    const float* W_k    = (const float*)d_in[9];
    const float* b_k    = (const float*)d_in[10];
    const float* W_eq   = (const float*)d_in[11];
    const float* b_eq   = (const float*)d_in[12];
    const float* W_ek   = (const float*)d_in[13];
    const float* b_ek   = (const float*)d_in[14];
    const float* W_ceq  = (const float*)d_in[15];
    const float* b_ceq  = (const float*)d_in[16];
    const float* W_cek  = (const float*)d_in[17];
    const float* b_cek  = (const float*)d_in[18];
    float* out = (float*)d_out;

    k_prep<<<384, 256>>>(x, W_emb, b_emb, W_q, b_q, W_k, b_k,
                         edge, cedge, W_eq, b_eq, W_ek, b_ek,
                         W_ceq, b_ceq, W_cek, b_cek);
    k_gextra<<<256, 256>>>(G, CG);
    k_attn<<<2048, 256>>>(out);
}

// round 14
// speedup vs baseline: 2.7037x; 1.0601x over previous
#include <cuda_runtime.h>
#include <cstdint>

#define Bsz 8
#define Nn 1024
#define Ee 256
#define Dm 64
#define Hh 4
#define DH 16

// fold 1/sqrt(64) * log2(e) into gq so scores feed ex2 directly
#define QSCALE 0.180336880520712f

// ---------------- device scratch ----------------
__device__ float d_e [4][Bsz][Hh][Ee][DH];        // eq, ek, ceq, cek
__device__ float d_g [2][2][Bsz][Hh][DH][Nn];     // [branch][q|k][b][h][c][n]
// fused emb->q/k weights: [qk][i][64] at 0/64/128/192, biases [qk][64] at 256/320
__device__ float d_wfold[384];

// ---------------- K1: edge projections + weight folding ----------------
// grid 129 x 256: bid<128 edge rows; bid==128 computes fused q/k weights.
__global__ void __launch_bounds__(256)
k_prep(const float* __restrict__ W_emb, const float* __restrict__ b_emb,
       const float* __restrict__ W_q,   const float* __restrict__ b_q,
       const float* __restrict__ W_k,   const float* __restrict__ b_k,
       const float* __restrict__ edge,  const float* __restrict__ cedge,
       const float* __restrict__ W_eq,  const float* __restrict__ b_eq,
       const float* __restrict__ W_ek,  const float* __restrict__ b_ek,
       const float* __restrict__ W_ceq, const float* __restrict__ b_ceq,
       const float* __restrict__ W_cek, const float* __restrict__ b_cek) {
    int tid = threadIdx.x;

    if (blockIdx.x < 128) {
        // ---------------- edge projections: 256 row-jobs per block ----------------
        __shared__ float sW4[1024];               // [4][16][16]
        __shared__ float sb4[64];                 // [4][16]
        {
            const float* Ws[4] = {W_eq, W_ek, W_ceq, W_cek};
            for (int l = tid; l < 1024; l += 256)
                sW4[l] = Ws[l >> 8][l & 255];
            if (tid < 64) {
                const float* Bs[4] = {b_eq, b_ek, b_ceq, b_cek};
                sb4[tid] = Bs[tid >> 4][tid & 15];
            }
        }
        __syncthreads();

        int i = blockIdx.x * 256 + tid;           // 0..32767
        int t = i >> 13;
        int r = i & 8191;
        const float* src = (t < 2 ? edge : cedge) + r * 16;
        float s[16];
#pragma unroll
        for (int j4 = 0; j4 < 4; ++j4) {
            float4 v = *(const float4*)(src + j4 * 4);
            s[j4 * 4 + 0] = v.x; s[j4 * 4 + 1] = v.y;
            s[j4 * 4 + 2] = v.z; s[j4 * 4 + 3] = v.w;
        }
        float acc[16];
#pragma unroll
        for (int cc = 0; cc < 16; ++cc) acc[cc] = sb4[t * 16 + cc];
#pragma unroll
        for (int j = 0; j < 16; ++j) {
            float sv = s[j];
#pragma unroll
            for (int cc = 0; cc < 16; ++cc)
                acc[cc] = fmaf(sv, sW4[t * 256 + j * 16 + cc], acc[cc]);
        }
        float* dst = (&d_e[0][0][0][0][0]) + (size_t)i * 16;
#pragma unroll
        for (int c4 = 0; c4 < 4; ++c4)
            *(float4*)(dst + c4 * 4) =
                make_float4(acc[c4 * 4], acc[c4 * 4 + 1], acc[c4 * 4 + 2], acc[c4 * 4 + 3]);
    } else {
        // ---------------- weight fold: W' = W_emb @ W_{q,k}; b' = b_emb @ W + b ----------------
        __shared__ float sWe[128];
        __shared__ float sbe[64];
        if (tid < 128) sWe[tid] = W_emb[tid];
        if (tid < 64)  sbe[tid] = b_emb[tid];
        __syncthreads();
        int c = tid & 63;
        int role = tid >> 6;                      // 0:(q,i0) 1:(q,i1) 2:(k,i0) 3:(k,i1)
        const float* W = (role < 2) ? W_q : W_k;
        int i = role & 1;
        float acc = 0.f;
#pragma unroll
        for (int j = 0; j < 64; ++j)
            acc = fmaf(sWe[i * 64 + j], W[j * 64 + c], acc);
        d_wfold[(role >> 1) * 128 + i * 64 + c] = acc;
        if ((role & 1) == 0) {
            const float* bb = (role == 0) ? b_q : b_k;
            float bacc = bb[c];
#pragma unroll
            for (int j = 0; j < 64; ++j)
                bacc = fmaf(sbe[j], W[j * 64 + c], bacc);
            d_wfold[256 + (role >> 1) * 64 + c] = bacc;
        }
    }
}

// ---------------- K3: gq/gk + div — prefetch mainloop + inline q/k from x ----------------
// grid: 2br * 8b * 16nt = 256 blocks; 256 threads = 16 c x 16 ns (4 n each).
__global__ void __launch_bounds__(256, 2)
k_gextra(const float* __restrict__ G, const float* __restrict__ CG,
         const float* __restrict__ x) {
    int bid = blockIdx.x;
    int nt = bid & 15;  bid >>= 4;
    int b  = bid & 7;   bid >>= 3;
    int br = bid;
    int tid = threadIdx.x;
    int c  = tid >> 4;          // 0..15
    int ns = tid & 15;          // 0..15 -> n = nbase + ns*4 + 0..3
    int nbase = nt * 64;

    const float* Gm  = (br ? CG : G) + (size_t)b * Ee * Nn;
    const float* eqb = &d_e[br * 2 + 0][b][0][0][0];   // [h][e][c], h-stride 4096
    const float* ekb = &d_e[br * 2 + 1][b][0][0][0];

    __shared__ float4 sg4[16][16];       // [ee][ns]
    __shared__ float  seq[4][16][16];    // [h][ee][c]  = 256 float4
    __shared__ float  sek[4][16][16];
    __shared__ float  swf[384];          // fused weights + biases
    __shared__ float  sx[128];           // x[b][nbase..nbase+63][2]
    float4* sq4 = (float4*)&seq[0][0][0];
    float4* sk4 = (float4*)&sek[0][0][0];

    // stage fused weights + x slice (synced by first loop barrier)
    if (tid < 128) sx[tid] = x[((size_t)b * Nn + nbase) * 2 + tid];
    for (int i = tid; i < 384; i += 256) swf[i] = d_wfold[i];

    // staging index split (one float4 per thread per array per tile)
    int ge = tid >> 4, gn = tid & 15;
    int h4 = tid >> 6, ee4 = (tid & 63) >> 2, c4 = tid & 3;
    const float* gsrc = Gm + (size_t)ge * Nn + nbase + gn * 4;
    size_t eoff = (size_t)(h4 * Ee + ee4) * DH + c4 * 4;

    float aq[4][4], ak[4][4];            // [h][n]
#pragma unroll
    for (int h = 0; h < 4; ++h)
#pragma unroll
        for (int j = 0; j < 4; ++j) { aq[h][j] = 0.f; ak[h][j] = 0.f; }
    float gs0 = 0.f, gs1 = 0.f, gs2 = 0.f, gs3 = 0.f;

    // preload tile 0
    float4 gpre = *(const float4*)(gsrc);
    float4 qpre = *(const float4*)(eqb + eoff);
    float4 kpre = *(const float4*)(ekb + eoff);

#pragma unroll 1
    for (int e0 = 0; e0 < Ee; e0 += 16) {
        sg4[ge][gn] = gpre;
        sq4[tid] = qpre;
        sk4[tid] = kpre;
        __syncthreads();
        if (e0 + 16 < Ee) {              // prefetch next tile (overlaps compute)
            gpre = *(const float4*)(gsrc + (size_t)(e0 + 16) * Nn);
            qpre = *(const float4*)(eqb + eoff + (size_t)(e0 + 16) * DH);
            kpre = *(const float4*)(ekb + eoff + (size_t)(e0 + 16) * DH);
        }
#pragma unroll
        for (int ee = 0; ee < 16; ++ee) {
            float4 g = sg4[ee][ns];
            gs0 += g.x; gs1 += g.y; gs2 += g.z; gs3 += g.w;
#pragma unroll
            for (int h = 0; h < 4; ++h) {
                float eqv = seq[h][ee][c];
                float ekv = sek[h][ee][c];
                aq[h][0] = fmaf(g.x, eqv, aq[h][0]);
                aq[h][1] = fmaf(g.y, eqv, aq[h][1]);
                aq[h][2] = fmaf(g.z, eqv, aq[h][2]);
                aq[h][3] = fmaf(g.w, eqv, aq[h][3]);
                ak[h][0] = fmaf(g.x, ekv, ak[h][0]);
                ak[h][1] = fmaf(g.y, ekv, ak[h][1]);
                ak[h][2] = fmaf(g.z, ekv, ak[h][2]);
                ak[h][3] = fmaf(g.w, ekv, ak[h][3]);
            }
        }
        __syncthreads();
    }
    float rd0 = 1.0f / gs0, rd1 = 1.0f / gs1, rd2 = 1.0f / gs2, rd3 = 1.0f / gs3;
    int n0 = nbase + ns * 4;

    // x pairs for this thread's 4 n
    float x0[4], x1[4];
#pragma unroll
    for (int nn = 0; nn < 4; ++nn) {
        x0[nn] = sx[(ns * 4 + nn) * 2 + 0];
        x1[nn] = sx[(ns * 4 + nn) * 2 + 1];
    }
#pragma unroll
    for (int h = 0; h < 4; ++h) {
        int ch = h * 16 + c;
        float wq0 = swf[ch],       wq1 = swf[64 + ch];
        float wk0 = swf[128 + ch], wk1 = swf[192 + ch];
        float bq  = swf[256 + ch], bk  = swf[320 + ch];
        float4 oq, ok;
        oq.x = (fmaf(x0[0], wq0, fmaf(x1[0], wq1, bq)) + aq[h][0] * rd0) * QSCALE;
        oq.y = (fmaf(x0[1], wq0, fmaf(x1[1], wq1, bq)) + aq[h][1] * rd1) * QSCALE;
        oq.z = (fmaf(x0[2], wq0, fmaf(x1[2], wq1, bq)) + aq[h][2] * rd2) * QSCALE;
        oq.w = (fmaf(x0[3], wq0, fmaf(x1[3], wq1, bq)) + aq[h][3] * rd3) * QSCALE;
        ok.x = (fmaf(x0[0], wk0, fmaf(x1[0], wk1, bk)) + ak[h][0] * rd0);
        ok.y = (fmaf(x0[1], wk0, fmaf(x1[1], wk1, bk)) + ak[h][1] * rd1);
        ok.z = (fmaf(x0[2], wk0, fmaf(x1[2], wk1, bk)) + ak[h][2] * rd2);
        ok.w = (fmaf(x0[3], wk0, fmaf(x1[3], wk1, bk)) + ak[h][3] * rd3);
        *(float4*)&d_g[br][0][b][h][c][n0] = oq;
        *(float4*)&d_g[br][1][b][h][c][n0] = ok;
    }
}

// ---------------- K4: scores + softmax — UNCHANGED (round-13 state) ----------------
#define RCHUNK 32
__global__ void __launch_bounds__(256, 2)
k_attn(float* __restrict__ out) {
    int bid = blockIdx.x;
    int chunk = bid & 31;  bid >>= 5;
    int h     = bid & 3;   bid >>= 2;
    int b     = bid & 7;   bid >>= 3;
    int br    = bid;
    int rbase = chunk * RCHUNK;

    const float* gq = &d_g[br][0][b][h][0][0];   // [c][n]
    const float* gk = &d_g[br][1][b][h][0][0];   // [c][n]

    __shared__ float sq[RCHUNK][20];
    __shared__ float spart[2][8][4];             // parity double-buffered

    int tid  = threadIdx.x;
    int warp = tid >> 5, lane = tid & 31;
    int col0 = warp * 128 + lane * 4;

    float4 kk[16];
#pragma unroll
    for (int c = 0; c < 16; ++c)
        kk[c] = *(const float4*)(gk + c * Nn + col0);

    for (int i = tid; i < RCHUNK * 16; i += 256) {
        int c = i >> 5, r = i & 31;
        sq[r][c] = gq[c * Nn + rbase + r];
    }
    __syncthreads();

    size_t obase = ((((size_t)br * Bsz + b) * Hh + h) * Nn + rbase) * (size_t)Nn;

#pragma unroll 1
    for (int wv = 0; wv < RCHUNK / 4; ++wv) {
        int r0 = wv * 4;
        float4 ex[4];
        float part[4];
#pragma unroll
        for (int rr = 0; rr < 4; ++rr) {
            const float* qp = &sq[r0 + rr][0];
            float4 qa = *(const float4*)(qp + 0);
            float4 qb = *(const float4*)(qp + 4);
            float4 qc = *(const float4*)(qp + 8);
            float4 qd = *(const float4*)(qp + 12);
            float qv[16] = {qa.x, qa.y, qa.z, qa.w, qb.x, qb.y, qb.z, qb.w,
                            qc.x, qc.y, qc.z, qc.w, qd.x, qd.y, qd.z, qd.w};
            float s0 = 0.f, s1 = 0.f, s2 = 0.f, s3 = 0.f;
#pragma unroll
            for (int c = 0; c < 16; ++c) {
                s0 = fmaf(qv[c], kk[c].x, s0);
                s1 = fmaf(qv[c], kk[c].y, s1);
                s2 = fmaf(qv[c], kk[c].z, s2);
                s3 = fmaf(qv[c], kk[c].w, s3);
            }
            float e0, e1, e2, e3;
            asm("ex2.approx.f32 %0, %1;" : "=f"(e0) : "f"(s0));
            asm("ex2.approx.f32 %0, %1;" : "=f"(e1) : "f"(s1));
            asm("ex2.approx.f32 %0, %1;" : "=f"(e2) : "f"(s2));
            asm("ex2.approx.f32 %0, %1;" : "=f"(e3) : "f"(s3));
            ex[rr] = make_float4(e0, e1, e2, e3);
            part[rr] = (e0 + e1) + (e2 + e3);
        }
#pragma unroll
        for (int o = 16; o; o >>= 1)
#pragma unroll
            for (int rr = 0; rr < 4; ++rr)
                part[rr] += __shfl_xor_sync(0xffffffffu, part[rr], o);
        int par = wv & 1;
        if (lane == 0) {
#pragma unroll
            for (int rr = 0; rr < 4; ++rr) spart[par][warp][rr] = part[rr];
        }
        __syncthreads();                         // single barrier per wave
#pragma unroll
        for (int rr = 0; rr < 4; ++rr) {
            float v = spart[par][lane & 7][rr];  // 8-way broadcast LDS
            v += __shfl_xor_sync(0xffffffffu, v, 1);
            v += __shfl_xor_sync(0xffffffffu, v, 2);
            v += __shfl_xor_sync(0xffffffffu, v, 4);
            float iv = 1.0f / v;
            float4 o4 = ex[rr];
            o4.x *= iv; o4.y *= iv; o4.z *= iv; o4.w *= iv;
            __stcs((float4*)(out + obase + (size_t)(r0 + rr) * Nn + col0), o4);
        }
    }
}

// ---------------- launcher ----------------
extern "C" void kernel_launch(void* const* d_in, const int* in_sizes, int n_in,
                              void* d_out, int out_size) {
    const float* x      = (const float*)d_in[0];
    const float* edge   = (const float*)d_in[1];
    const float* cedge  = (const float*)d_in[2];
    const float* G      = (const float*)d_in[3];
    const float* CG     = (const float*)d_in[4];
    const float* W_emb  = (const float*)d_in[5];
    const float* b_emb  = (const float*)d_in[6];
    const float* W_q    = (const float*)d_in[7];
    const float* b_q    = (const float*)d_in[8];
    const float* W_k    = (const float*)d_in[9];
    const float* b_k    = (const float*)d_in[10];
    const float* W_eq   = (const float*)d_in[11];
    const float* b_eq   = (const float*)d_in[12];
    const float* W_ek   = (const float*)d_in[13];
    const float* b_ek   = (const float*)d_in[14];
    const float* W_ceq  = (const float*)d_in[15];
    const float* b_ceq  = (const float*)d_in[16];
    const float* W_cek  = (const float*)d_in[17];
    const float* b_cek  = (const float*)d_in[18];
    float* out = (float*)d_out;

    k_prep<<<129, 256>>>(W_emb, b_emb, W_q, b_q, W_k, b_k,
                         edge, cedge, W_eq, b_eq, W_ek, b_ek,
                         W_ceq, b_ceq, W_cek, b_cek);
    k_gextra<<<256, 256>>>(G, CG, x);
    k_attn<<<2048, 256>>>(out);
}

// round 15
// speedup vs baseline: 2.7334x; 1.0110x over previous
#include <cuda_runtime.h>
#include <cstdint>

#define Bsz 8
#define Nn 1024
#define Ee 256
#define Dm 64
#define Hh 4
#define DH 16

// fold 1/sqrt(64) * log2(e) into gq so scores feed ex2 directly
#define QSCALE 0.180336880520712f

// ---------------- device scratch ----------------
__device__ float d_e [4][Bsz][Hh][Ee][DH];        // eq, ek, ceq, cek
__device__ float d_g [2][2][Bsz][Hh][DH][Nn];     // [branch][q|k][b][h][c][n]
// fused emb->q/k weights: [qk][i][64] at 0/64/128/192, biases [qk][64] at 256/320
__device__ float d_wfold[384];

// ---------------- K1: edge projections + weight folding ----------------
// grid 129 x 256: bid<128 edge rows; bid==128 computes fused q/k weights.
__global__ void __launch_bounds__(256)
k_prep(const float* __restrict__ W_emb, const float* __restrict__ b_emb,
       const float* __restrict__ W_q,   const float* __restrict__ b_q,
       const float* __restrict__ W_k,   const float* __restrict__ b_k,
       const float* __restrict__ edge,  const float* __restrict__ cedge,
       const float* __restrict__ W_eq,  const float* __restrict__ b_eq,
       const float* __restrict__ W_ek,  const float* __restrict__ b_ek,
       const float* __restrict__ W_ceq, const float* __restrict__ b_ceq,
       const float* __restrict__ W_cek, const float* __restrict__ b_cek) {
    int tid = threadIdx.x;

    if (blockIdx.x < 128) {
        // ---------------- edge projections: 256 row-jobs per block ----------------
        __shared__ float sW4[1024];               // [4][16][16]
        __shared__ float sb4[64];                 // [4][16]
        {
            const float* Ws[4] = {W_eq, W_ek, W_ceq, W_cek};
            for (int l = tid; l < 1024; l += 256)
                sW4[l] = Ws[l >> 8][l & 255];
            if (tid < 64) {
                const float* Bs[4] = {b_eq, b_ek, b_ceq, b_cek};
                sb4[tid] = Bs[tid >> 4][tid & 15];
            }
        }
        __syncthreads();

        int i = blockIdx.x * 256 + tid;           // 0..32767
        int t = i >> 13;
        int r = i & 8191;
        const float* src = (t < 2 ? edge : cedge) + r * 16;
        float s[16];
#pragma unroll
        for (int j4 = 0; j4 < 4; ++j4) {
            float4 v = *(const float4*)(src + j4 * 4);
            s[j4 * 4 + 0] = v.x; s[j4 * 4 + 1] = v.y;
            s[j4 * 4 + 2] = v.z; s[j4 * 4 + 3] = v.w;
        }
        float acc[16];
#pragma unroll
        for (int cc = 0; cc < 16; ++cc) acc[cc] = sb4[t * 16 + cc];
#pragma unroll
        for (int j = 0; j < 16; ++j) {
            float sv = s[j];
#pragma unroll
            for (int cc = 0; cc < 16; ++cc)
                acc[cc] = fmaf(sv, sW4[t * 256 + j * 16 + cc], acc[cc]);
        }
        float* dst = (&d_e[0][0][0][0][0]) + (size_t)i * 16;
#pragma unroll
        for (int c4 = 0; c4 < 4; ++c4)
            *(float4*)(dst + c4 * 4) =
                make_float4(acc[c4 * 4], acc[c4 * 4 + 1], acc[c4 * 4 + 2], acc[c4 * 4 + 3]);
    } else {
        // ---------------- weight fold: W' = W_emb @ W_{q,k}; b' = b_emb @ W + b ----------------
        __shared__ float sWe[128];
        __shared__ float sbe[64];
        if (tid < 128) sWe[tid] = W_emb[tid];
        if (tid < 64)  sbe[tid] = b_emb[tid];
        __syncthreads();
        int c = tid & 63;
        int role = tid >> 6;                      // 0:(q,i0) 1:(q,i1) 2:(k,i0) 3:(k,i1)
        const float* W = (role < 2) ? W_q : W_k;
        int i = role & 1;
        float acc = 0.f;
#pragma unroll
        for (int j = 0; j < 64; ++j)
            acc = fmaf(sWe[i * 64 + j], W[j * 64 + c], acc);
        d_wfold[(role >> 1) * 128 + i * 64 + c] = acc;
        if ((role & 1) == 0) {
            const float* bb = (role == 0) ? b_q : b_k;
            float bacc = bb[c];
#pragma unroll
            for (int j = 0; j < 64; ++j)
                bacc = fmaf(sbe[j], W[j * 64 + c], bacc);
            d_wfold[256 + (role >> 1) * 64 + c] = bacc;
        }
    }
}

// ---------------- K3: gq/gk + div — prefetch mainloop + inline q/k from x ----------------
// grid: 8b * 16nt = 128 blocks (per branch); 256 threads = 16 c x 16 ns (4 n each).
__global__ void __launch_bounds__(256, 2)
k_gextra(const float* __restrict__ G, const float* __restrict__ CG,
         const float* __restrict__ x, int br) {
    int bid = blockIdx.x;
    int nt = bid & 15;  bid >>= 4;
    int b  = bid & 7;
    int tid = threadIdx.x;
    int c  = tid >> 4;          // 0..15
    int ns = tid & 15;          // 0..15 -> n = nbase + ns*4 + 0..3
    int nbase = nt * 64;

    const float* Gm  = (br ? CG : G) + (size_t)b * Ee * Nn;
    const float* eqb = &d_e[br * 2 + 0][b][0][0][0];   // [h][e][c], h-stride 4096
    const float* ekb = &d_e[br * 2 + 1][b][0][0][0];

    __shared__ float4 sg4[16][16];       // [ee][ns]
    __shared__ float  seq[4][16][16];    // [h][ee][c]  = 256 float4
    __shared__ float  sek[4][16][16];
    __shared__ float  swf[384];          // fused weights + biases
    __shared__ float  sx[128];           // x[b][nbase..nbase+63][2]
    float4* sq4 = (float4*)&seq[0][0][0];
    float4* sk4 = (float4*)&sek[0][0][0];

    // stage fused weights + x slice (synced by first loop barrier)
    if (tid < 128) sx[tid] = x[((size_t)b * Nn + nbase) * 2 + tid];
    for (int i = tid; i < 384; i += 256) swf[i] = d_wfold[i];

    // staging index split (one float4 per thread per array per tile)
    int ge = tid >> 4, gn = tid & 15;
    int h4 = tid >> 6, ee4 = (tid & 63) >> 2, c4 = tid & 3;
    const float* gsrc = Gm + (size_t)ge * Nn + nbase + gn * 4;
    size_t eoff = (size_t)(h4 * Ee + ee4) * DH + c4 * 4;

    float aq[4][4], ak[4][4];            // [h][n]
#pragma unroll
    for (int h = 0; h < 4; ++h)
#pragma unroll
        for (int j = 0; j < 4; ++j) { aq[h][j] = 0.f; ak[h][j] = 0.f; }
    float gs0 = 0.f, gs1 = 0.f, gs2 = 0.f, gs3 = 0.f;

    // preload tile 0
    float4 gpre = *(const float4*)(gsrc);
    float4 qpre = *(const float4*)(eqb + eoff);
    float4 kpre = *(const float4*)(ekb + eoff);

#pragma unroll 1
    for (int e0 = 0; e0 < Ee; e0 += 16) {
        sg4[ge][gn] = gpre;
        sq4[tid] = qpre;
        sk4[tid] = kpre;
        __syncthreads();
        if (e0 + 16 < Ee) {              // prefetch next tile (overlaps compute)
            gpre = *(const float4*)(gsrc + (size_t)(e0 + 16) * Nn);
            qpre = *(const float4*)(eqb + eoff + (size_t)(e0 + 16) * DH);
            kpre = *(const float4*)(ekb + eoff + (size_t)(e0 + 16) * DH);
        }
#pragma unroll
        for (int ee = 0; ee < 16; ++ee) {
            float4 g = sg4[ee][ns];
            gs0 += g.x; gs1 += g.y; gs2 += g.z; gs3 += g.w;
#pragma unroll
            for (int h = 0; h < 4; ++h) {
                float eqv = seq[h][ee][c];
                float ekv = sek[h][ee][c];
                aq[h][0] = fmaf(g.x, eqv, aq[h][0]);
                aq[h][1] = fmaf(g.y, eqv, aq[h][1]);
                aq[h][2] = fmaf(g.z, eqv, aq[h][2]);
                aq[h][3] = fmaf(g.w, eqv, aq[h][3]);
                ak[h][0] = fmaf(g.x, ekv, ak[h][0]);
                ak[h][1] = fmaf(g.y, ekv, ak[h][1]);
                ak[h][2] = fmaf(g.z, ekv, ak[h][2]);
                ak[h][3] = fmaf(g.w, ekv, ak[h][3]);
            }
        }
        __syncthreads();
    }
    float rd0 = 1.0f / gs0, rd1 = 1.0f / gs1, rd2 = 1.0f / gs2, rd3 = 1.0f / gs3;
    int n0 = nbase + ns * 4;

    // x pairs for this thread's 4 n
    float x0[4], x1[4];
#pragma unroll
    for (int nn = 0; nn < 4; ++nn) {
        x0[nn] = sx[(ns * 4 + nn) * 2 + 0];
        x1[nn] = sx[(ns * 4 + nn) * 2 + 1];
    }
#pragma unroll
    for (int h = 0; h < 4; ++h) {
        int ch = h * 16 + c;
        float wq0 = swf[ch],       wq1 = swf[64 + ch];
        float wk0 = swf[128 + ch], wk1 = swf[192 + ch];
        float bq  = swf[256 + ch], bk  = swf[320 + ch];
        float4 oq, ok;
        oq.x = (fmaf(x0[0], wq0, fmaf(x1[0], wq1, bq)) + aq[h][0] * rd0) * QSCALE;
        oq.y = (fmaf(x0[1], wq0, fmaf(x1[1], wq1, bq)) + aq[h][1] * rd1) * QSCALE;
        oq.z = (fmaf(x0[2], wq0, fmaf(x1[2], wq1, bq)) + aq[h][2] * rd2) * QSCALE;
        oq.w = (fmaf(x0[3], wq0, fmaf(x1[3], wq1, bq)) + aq[h][3] * rd3) * QSCALE;
        ok.x = (fmaf(x0[0], wk0, fmaf(x1[0], wk1, bk)) + ak[h][0] * rd0);
        ok.y = (fmaf(x0[1], wk0, fmaf(x1[1], wk1, bk)) + ak[h][1] * rd1);
        ok.z = (fmaf(x0[2], wk0, fmaf(x1[2], wk1, bk)) + ak[h][2] * rd2);
        ok.w = (fmaf(x0[3], wk0, fmaf(x1[3], wk1, bk)) + ak[h][3] * rd3);
        *(float4*)&d_g[br][0][b][h][c][n0] = oq;
        *(float4*)&d_g[br][1][b][h][c][n0] = ok;
    }
}

// ---------------- K4: scores + softmax — per-branch grid (body unchanged) ----------------
#define RCHUNK 32
__global__ void __launch_bounds__(256, 2)
k_attn(float* __restrict__ out, int br) {
    int bid = blockIdx.x;
    int chunk = bid & 31;  bid >>= 5;
    int h     = bid & 3;   bid >>= 2;
    int b     = bid & 7;
    int rbase = chunk * RCHUNK;

    const float* gq = &d_g[br][0][b][h][0][0];   // [c][n]
    const float* gk = &d_g[br][1][b][h][0][0];   // [c][n]

    __shared__ float sq[RCHUNK][20];
    __shared__ float spart[2][8][4];             // parity double-buffered

    int tid  = threadIdx.x;
    int warp = tid >> 5, lane = tid & 31;
    int col0 = warp * 128 + lane * 4;

    float4 kk[16];
#pragma unroll
    for (int c = 0; c < 16; ++c)
        kk[c] = *(const float4*)(gk + c * Nn + col0);

    for (int i = tid; i < RCHUNK * 16; i += 256) {
        int c = i >> 5, r = i & 31;
        sq[r][c] = gq[c * Nn + rbase + r];
    }
    __syncthreads();

    size_t obase = ((((size_t)br * Bsz + b) * Hh + h) * Nn + rbase) * (size_t)Nn;

#pragma unroll 1
    for (int wv = 0; wv < RCHUNK / 4; ++wv) {
        int r0 = wv * 4;
        float4 ex[4];
        float part[4];
#pragma unroll
        for (int rr = 0; rr < 4; ++rr) {
            const float* qp = &sq[r0 + rr][0];
            float4 qa = *(const float4*)(qp + 0);
            float4 qb = *(const float4*)(qp + 4);
            float4 qc = *(const float4*)(qp + 8);
            float4 qd = *(const float4*)(qp + 12);
            float qv[16] = {qa.x, qa.y, qa.z, qa.w, qb.x, qb.y, qb.z, qb.w,
                            qc.x, qc.y, qc.z, qc.w, qd.x, qd.y, qd.z, qd.w};
            float s0 = 0.f, s1 = 0.f, s2 = 0.f, s3 = 0.f;
#pragma unroll
            for (int c = 0; c < 16; ++c) {
                s0 = fmaf(qv[c], kk[c].x, s0);
                s1 = fmaf(qv[c], kk[c].y, s1);
                s2 = fmaf(qv[c], kk[c].z, s2);
                s3 = fmaf(qv[c], kk[c].w, s3);
            }
            float e0, e1, e2, e3;
            asm("ex2.approx.f32 %0, %1;" : "=f"(e0) : "f"(s0));
            asm("ex2.approx.f32 %0, %1;" : "=f"(e1) : "f"(s1));
            asm("ex2.approx.f32 %0, %1;" : "=f"(e2) : "f"(s2));
            asm("ex2.approx.f32 %0, %1;" : "=f"(e3) : "f"(s3));
            ex[rr] = make_float4(e0, e1, e2, e3);
            part[rr] = (e0 + e1) + (e2 + e3);
        }
#pragma unroll
        for (int o = 16; o; o >>= 1)
#pragma unroll
            for (int rr = 0; rr < 4; ++rr)
                part[rr] += __shfl_xor_sync(0xffffffffu, part[rr], o);
        int par = wv & 1;
        if (lane == 0) {
#pragma unroll
            for (int rr = 0; rr < 4; ++rr) spart[par][warp][rr] = part[rr];
        }
        __syncthreads();                         // single barrier per wave
#pragma unroll
        for (int rr = 0; rr < 4; ++rr) {
            float v = spart[par][lane & 7][rr];  // 8-way broadcast LDS
            v += __shfl_xor_sync(0xffffffffu, v, 1);
            v += __shfl_xor_sync(0xffffffffu, v, 2);
            v += __shfl_xor_sync(0xffffffffu, v, 4);
            float iv = 1.0f / v;
            float4 o4 = ex[rr];
            o4.x *= iv; o4.y *= iv; o4.z *= iv; o4.w *= iv;
            __stcs((float4*)(out + obase + (size_t)(r0 + rr) * Nn + col0), o4);
        }
    }
}

// ---------------- launcher: dual-stream branch pipeline ----------------
extern "C" void kernel_launch(void* const* d_in, const int* in_sizes, int n_in,
                              void* d_out, int out_size) {
    const float* x      = (const float*)d_in[0];
    const float* edge   = (const float*)d_in[1];
    const float* cedge  = (const float*)d_in[2];
    const float* G      = (const float*)d_in[3];
    const float* CG     = (const float*)d_in[4];
    const float* W_emb  = (const float*)d_in[5];
    const float* b_emb  = (const float*)d_in[6];
    const float* W_q    = (const float*)d_in[7];
    const float* b_q    = (const float*)d_in[8];
    const float* W_k    = (const float*)d_in[9];
    const float* b_k    = (const float*)d_in[10];
    const float* W_eq   = (const float*)d_in[11];
    const float* b_eq   = (const float*)d_in[12];
    const float* W_ek   = (const float*)d_in[13];
    const float* b_ek   = (const float*)d_in[14];
    const float* W_ceq  = (const float*)d_in[15];
    const float* b_ceq  = (const float*)d_in[16];
    const float* W_cek  = (const float*)d_in[17];
    const float* b_cek  = (const float*)d_in[18];
    float* out = (float*)d_out;

    static cudaStream_t sA = nullptr, sB = nullptr;
    static cudaEvent_t evRoot, evPrep, evA, evB;
    if (!sA) {
        cudaStreamCreateWithFlags(&sA, cudaStreamNonBlocking);
        cudaStreamCreateWithFlags(&sB, cudaStreamNonBlocking);
        cudaEventCreateWithFlags(&evRoot, cudaEventDisableTiming);
        cudaEventCreateWithFlags(&evPrep, cudaEventDisableTiming);
        cudaEventCreateWithFlags(&evA,    cudaEventDisableTiming);
        cudaEventCreateWithFlags(&evB,    cudaEventDisableTiming);
    }

    // fork from the capture (default) stream
    cudaEventRecord(evRoot, 0);
    cudaStreamWaitEvent(sA, evRoot, 0);

    k_prep<<<129, 256, 0, sA>>>(W_emb, b_emb, W_q, b_q, W_k, b_k,
                                edge, cedge, W_eq, b_eq, W_ek, b_ek,
                                W_ceq, b_ceq, W_cek, b_cek);
    cudaEventRecord(evPrep, sA);
    cudaStreamWaitEvent(sB, evPrep, 0);

    // chain A: branch 0
    k_gextra<<<128, 256, 0, sA>>>(G, CG, x, 0);
    k_attn<<<1024, 256, 0, sA>>>(out, 0);
    cudaEventRecord(evA, sA);

    // chain B: branch 1
    k_gextra<<<128, 256, 0, sB>>>(G, CG, x, 1);
    k_attn<<<1024, 256, 0, sB>>>(out, 1);
    cudaEventRecord(evB, sB);

    // join back to the capture stream
    cudaStreamWaitEvent(0, evA, 0);
    cudaStreamWaitEvent(0, evB, 0);
}